// round 4
// baseline (speedup 1.0000x reference)
#include <cuda_runtime.h>
#include <cstdint>

// Problem dims (fixed)
#define BB   16
#define HH   64
#define WWD  64
#define TT   4096
#define CC   256
#define NCH  32          // chunks per scan
#define CLEN 128         // T / NCH
#define NELEM (BB*TT*CC) // 16777216
#define NAGG  (BB*NCH*CC)

// ---------------- scratch (device globals; no allocation allowed) ------------
__device__ float g_xs[NELEM];
__device__ float g_k [NELEM];
__device__ float g_v [NELEM];
__device__ float g_sr[NELEM];
// per-t local backward scan states (indexed by sequence position s)
__device__ float g_bA[NELEM];
__device__ float g_bB[NELEM];
__device__ float g_bP[NELEM];
// chunk aggregates / prefixes / suffixes
__device__ float g_fA[NAGG], g_fB[NAGG], g_fP[NAGG];     // fwd chunk aggregates
__device__ float g_bAg[NAGG], g_bBg[NAGG], g_bPg[NAGG];  // bwd chunk aggregates
__device__ float g_pA[NAGG], g_pB[NAGG], g_pP[NAGG];     // fwd chunk prefixes (carry at chunk start)
__device__ float g_sA[NAGG], g_sB[NAGG], g_sP[NAGG];     // bwd chunk suffixes (anchored at chunk end)

// sequence-position -> memory-row map. JM=0: row-major (t=s). JM=1: column-major
// (s = w*H + h  ->  t = h*W + w)
template<int JM>
__device__ __forceinline__ int seqmap(int s) {
    return (JM == 0) ? s : (((s & 63) << 6) | (s >> 6));
}

// ---------------- omni_shift: fused 5x5 depthwise stencil --------------------
__global__ __launch_bounds__(256) void omni_kernel(
    const float* __restrict__ x, const float* __restrict__ alpha,
    const float* __restrict__ w1, const float* __restrict__ w3,
    const float* __restrict__ w5)
{
    int c = threadIdx.x;            // 0..255
    int b = blockIdx.x >> 6;        // grid = BB*WWD
    int w = blockIdx.x & 63;

    float a0 = alpha[0], a1 = alpha[1], a2 = alpha[2], a3 = alpha[3];

    float coef[5][5];
    #pragma unroll
    for (int r = 0; r < 5; r++)
        #pragma unroll
        for (int d = 0; d < 5; d++)
            coef[r][d] = a3 * w5[c * 25 + r * 5 + d];
    #pragma unroll
    for (int r = 0; r < 3; r++)
        #pragma unroll
        for (int d = 0; d < 3; d++)
            coef[r + 1][d + 1] += a2 * w3[c * 9 + r * 3 + d];
    coef[2][2] += a0 + a1 * w1[c];

    const float* xb = x + (size_t)b * TT * CC + c;
    float* ob = g_xs + (size_t)b * TT * CC + c;

    float win[5][5];
    // prime rows h-2 .. h+2 for h = 0
    #pragma unroll
    for (int r = 0; r < 5; r++) {
        int hr = r - 2;
        #pragma unroll
        for (int d = 0; d < 5; d++) {
            int wx = w + d - 2;
            win[r][d] = (hr >= 0 && wx >= 0 && wx < WWD) ? xb[(hr * WWD + wx) * CC] : 0.0f;
        }
    }

    for (int h = 0; h < HH; h++) {
        float acc = 0.0f;
        #pragma unroll
        for (int r = 0; r < 5; r++)
            #pragma unroll
            for (int d = 0; d < 5; d++)
                acc = fmaf(coef[r][d], win[r][d], acc);
        ob[(h * WWD + w) * CC] = acc;
        // shift window up, load row h+3
        #pragma unroll
        for (int r = 0; r < 4; r++)
            #pragma unroll
            for (int d = 0; d < 5; d++)
                win[r][d] = win[r + 1][d];
        int hr = h + 3;
        #pragma unroll
        for (int d = 0; d < 5; d++) {
            int wx = w + d - 2;
            win[4][d] = (hr < HH && wx >= 0 && wx < WWD) ? xb[(hr * WWD + wx) * CC] : 0.0f;
        }
    }
}

// ---------------- fp32 SGEMM, 128x128x16 tiles, 8x8 microtiles ---------------
// MODE 0: A = g_xs [M,256]; bx 0..5 -> {Wk|Wv|Wr} columns, writes g_k/g_v/g_sr
//         (sigmoid on the Wr part).
// MODE 1: A = g_sr * g_v elementwise; B = Wo; writes outp.
template<int MODE>
__global__ __launch_bounds__(256) void gemm_kernel(
    const float* __restrict__ W0, const float* __restrict__ W1,
    const float* __restrict__ W2, float* __restrict__ outp)
{
    __shared__ float As[16][132];   // [k][m], padded
    __shared__ float Bs[16][128];   // [k][n]

    int tid = threadIdx.x;
    int bx = blockIdx.x;
    int by = blockIdx.y;

    const float* Bsrc;
    float* Dst;
    int ncol0;
    bool sig = false;
    if (MODE == 0) {
        Bsrc  = (bx < 2) ? W0 : (bx < 4) ? W1 : W2;
        Dst   = (bx < 2) ? g_k : (bx < 4) ? g_v : g_sr;
        sig   = (bx >= 4);
        ncol0 = (bx & 1) * 128;
    } else {
        Bsrc  = W0;
        Dst   = outp;
        ncol0 = bx * 128;
    }

    int m0 = by * 128;
    int tx = tid & 15, ty = tid >> 4;

    float acc[8][8];
    #pragma unroll
    for (int i = 0; i < 8; i++)
        #pragma unroll
        for (int j = 0; j < 8; j++)
            acc[i][j] = 0.0f;

    for (int kb = 0; kb < 16; ++kb) {
        int k0 = kb * 16;
        float4 afr[2], bfr[2];
        #pragma unroll
        for (int q = 0; q < 2; q++) {
            int id = tid + q * 256;
            int ar = id >> 2, ac = (id & 3) * 4;
            int aidx = (m0 + ar) * CC + k0 + ac;
            if (MODE == 0) {
                afr[q] = *(const float4*)&g_xs[aidx];
            } else {
                float4 s4 = *(const float4*)&g_sr[aidx];
                float4 v4 = *(const float4*)&g_v[aidx];
                afr[q] = make_float4(s4.x * v4.x, s4.y * v4.y, s4.z * v4.z, s4.w * v4.w);
            }
            int br = id >> 5, bc = (id & 31) * 4;
            bfr[q] = *(const float4*)&Bsrc[(k0 + br) * CC + ncol0 + bc];
        }
        __syncthreads();   // previous iteration's compute done
        #pragma unroll
        for (int q = 0; q < 2; q++) {
            int id = tid + q * 256;
            int ar = id >> 2, ac = (id & 3) * 4;
            As[ac + 0][ar] = afr[q].x;
            As[ac + 1][ar] = afr[q].y;
            As[ac + 2][ar] = afr[q].z;
            As[ac + 3][ar] = afr[q].w;
            int br = id >> 5, bc = (id & 31) * 4;
            *(float4*)&Bs[br][bc] = bfr[q];
        }
        __syncthreads();
        #pragma unroll
        for (int kk = 0; kk < 16; kk++) {
            float ra[8], rb[8];
            *(float4*)&ra[0] = *(const float4*)&As[kk][ty * 8];
            *(float4*)&ra[4] = *(const float4*)&As[kk][ty * 8 + 4];
            *(float4*)&rb[0] = *(const float4*)&Bs[kk][tx * 8];
            *(float4*)&rb[4] = *(const float4*)&Bs[kk][tx * 8 + 4];
            #pragma unroll
            for (int i = 0; i < 8; i++)
                #pragma unroll
                for (int j = 0; j < 8; j++)
                    acc[i][j] = fmaf(ra[i], rb[j], acc[i][j]);
        }
    }

    #pragma unroll
    for (int i = 0; i < 8; i++) {
        int m = m0 + ty * 8 + i;
        float* pp = Dst + m * CC + ncol0 + tx * 8;
        float vals[8];
        #pragma unroll
        for (int j = 0; j < 8; j++) {
            float vv = acc[i][j];
            vals[j] = sig ? (1.0f / (1.0f + __expf(-vv))) : vv;
        }
        *(float4*)&pp[0] = *(float4*)&vals[0];
        *(float4*)&pp[4] = *(float4*)&vals[4];
    }
}

// ---------------- scan phase 1: chunk aggregates + local bwd states ----------
// grid = BB*NCH blocks, 256 threads (= c)
template<int JM>
__global__ __launch_bounds__(256) void scan_p1(const float* __restrict__ sd, int j)
{
    int c  = threadIdx.x;
    int b  = blockIdx.x >> 5;
    int ch = blockIdx.x & 31;
    float wneg = -__expf(sd[j * CC + c] * (1.0f / 4096.0f));
    int base = b * TT * CC + c;
    int s0 = ch * CLEN;

    // forward aggregate over [s0, s0+CLEN), "end" anchored at s0+CLEN
    float a = 0.0f, bb = 0.0f, p = -1e38f;
    #pragma unroll 4
    for (int i = 0; i < CLEN; i++) {
        int s = s0 + i;
        int t = seqmap<JM>(s);
        float kt = g_k[base + t * CC];
        float vt = g_v[base + t * CC];
        float q = fmaxf(p + wneg, kt);
        float e1 = __expf(p + wneg - q);
        float e2 = __expf(kt - q);
        a = e1 * a + e2 * vt; bb = e1 * bb + e2; p = q;
    }
    int ai = (b * NCH + ch) * CC + c;
    g_fA[ai] = a; g_fB[ai] = bb; g_fP[ai] = p;

    // backward: emit pre-update carry at each s (local suffix over (s, s1),
    // anchored s+1), final carry = chunk aggregate anchored at s0
    a = 0.0f; bb = 0.0f; p = -1e38f;
    #pragma unroll 4
    for (int i = CLEN - 1; i >= 0; i--) {
        int s = s0 + i;
        int t = seqmap<JM>(s);
        float kt = g_k[base + t * CC];
        float vt = g_v[base + t * CC];
        int si = base + s * CC;
        g_bA[si] = a; g_bB[si] = bb; g_bP[si] = p;
        float q = fmaxf(p + wneg, kt);
        float e1 = __expf(p + wneg - q);
        float e2 = __expf(kt - q);
        a = e1 * a + e2 * vt; bb = e1 * bb + e2; p = q;
    }
    g_bAg[ai] = a; g_bBg[ai] = bb; g_bPg[ai] = p;
}

// ---------------- scan phase 2: cross-chunk prefixes / suffixes --------------
// grid = 16 blocks x 256 threads = one thread per (b,c)
__global__ __launch_bounds__(256) void scan_p2(const float* __restrict__ sd, int j)
{
    int idx = blockIdx.x * 256 + threadIdx.x;
    int b = idx >> 8;
    int c = idx & 255;
    float wneg = -__expf(sd[j * CC + c] * (1.0f / 4096.0f));
    float dec = (float)CLEN * wneg;

    // fwd exclusive chunk prefixes (carry state at chunk start)
    float a = 0.0f, bb = 0.0f, p = -1e38f;
    for (int ch = 0; ch < NCH; ch++) {
        int ai = (b * NCH + ch) * CC + c;
        g_pA[ai] = a; g_pB[ai] = bb; g_pP[ai] = p;
        float Aag = g_fA[ai], Bag = g_fB[ai], Pag = g_fP[ai];
        float q = fmaxf(p + dec, Pag);
        float e1 = __expf(p + dec - q), e2 = __expf(Pag - q);
        a = e1 * a + e2 * Aag; bb = e1 * bb + e2 * Bag; p = q;
    }
    // bwd exclusive chunk suffixes (anchored at chunk end)
    a = 0.0f; bb = 0.0f; p = -1e38f;
    for (int ch = NCH - 1; ch >= 0; ch--) {
        int ai = (b * NCH + ch) * CC + c;
        g_sA[ai] = a; g_sB[ai] = bb; g_sP[ai] = p;
        float Aag = g_bAg[ai], Bag = g_bBg[ai], Pag = g_bPg[ai];
        float q = fmaxf(Pag, p + dec);
        float e1 = __expf(Pag - q), e2 = __expf(p + dec - q);
        a = e1 * Aag + e2 * a; bb = e1 * Bag + e2 * bb; p = q;
    }
}

// ---------------- scan phase 3: fwd scan + 4-way combine, write v in place ---
template<int JM>
__global__ __launch_bounds__(256) void scan_p3(
    const float* __restrict__ sd, const float* __restrict__ sf, int j)
{
    int c  = threadIdx.x;
    int b  = blockIdx.x >> 5;
    int ch = blockIdx.x & 31;
    float wneg = -__expf(sd[j * CC + c] * (1.0f / 4096.0f));
    float u = sf[j * CC + c] * (1.0f / 4096.0f);
    int base = b * TT * CC + c;
    int ai = (b * NCH + ch) * CC + c;

    float af = g_pA[ai], bf = g_pB[ai], pf = g_pP[ai];   // fwd carry seeded by prefix
    float Asf = g_sA[ai], Bsf = g_sB[ai], Psf = g_sP[ai]; // bwd suffix (anchored chunk end)
    int s0 = ch * CLEN;

    #pragma unroll 2
    for (int i = 0; i < CLEN; i++) {
        int s = s0 + i;
        int t = seqmap<JM>(s);
        int ti = base + t * CC;
        int si = base + s * CC;
        float kt = g_k[ti];
        float vt = g_v[ti];
        float al = g_bA[si], bl = g_bB[si], pl = g_bP[si];

        // suffix contribution shifted to anchor s+1
        float dcy = Psf + (float)(CLEN - 1 - i) * wneg;
        float ps = u + kt;
        float q = fmaxf(fmaxf(pf, pl), fmaxf(dcy, ps));
        float ef = __expf(pf - q);
        float el = __expf(pl - q);
        float ed = __expf(dcy - q);
        float es = __expf(ps - q);
        float num = ef * af + el * al + ed * Asf + es * vt;
        float den = ef * bf + el * bl + ed * Bsf + es;
        g_v[ti] = num / den;

        // forward carry update (uses original vt)
        float qn = fmaxf(pf + wneg, kt);
        float e1 = __expf(pf + wneg - qn);
        float e2 = __expf(kt - qn);
        af = e1 * af + e2 * vt; bf = e1 * bf + e2; pf = qn;
    }
}

// ---------------- launcher ---------------------------------------------------
extern "C" void kernel_launch(void* const* d_in, const int* in_sizes, int n_in,
                              void* d_out, int out_size)
{
    const float *x = nullptr, *alpha = nullptr, *w1 = nullptr, *w3 = nullptr, *w5 = nullptr;
    const float* Wm[4] = {nullptr, nullptr, nullptr, nullptr}; // Wk, Wv, Wr, Wo (in order)
    const float* S2[2] = {nullptr, nullptr};                   // spatial_decay, spatial_first
    int nW = 0, nS = 0;
    for (int i = 0; i < n_in; i++) {
        int sz = in_sizes[i];
        const float* p = (const float*)d_in[i];
        if      (sz == NELEM) x = p;
        else if (sz == 4)     alpha = p;
        else if (sz == 256)   w1 = p;
        else if (sz == 2304)  w3 = p;
        else if (sz == 6400)  w5 = p;
        else if (sz == 65536) { if (nW < 4) Wm[nW++] = p; }
        else if (sz == 512)   { if (nS < 2) S2[nS++] = p; }
        // size-1 scalars (height/width) ignored — dims are compile-time
    }

    // 1. omni_shift -> g_xs
    omni_kernel<<<BB * WWD, 256>>>(x, alpha, w1, w3, w5);

    // 2. fused k/v/sigmoid(r) GEMMs
    gemm_kernel<0><<<dim3(6, 512), 256>>>(Wm[0], Wm[1], Wm[2], nullptr);

    // 3. rec 0: H-scan (row-major)
    scan_p1<0><<<BB * NCH, 256>>>(S2[0], 0);
    scan_p2<<<16, 256>>>(S2[0], 0);
    scan_p3<0><<<BB * NCH, 256>>>(S2[0], S2[1], 0);

    // 4. rec 1: W-scan (column-major)
    scan_p1<1><<<BB * NCH, 256>>>(S2[0], 1);
    scan_p2<<<16, 256>>>(S2[0], 1);
    scan_p3<1><<<BB * NCH, 256>>>(S2[0], S2[1], 1);

    // 5. (sr * v) @ Wo -> d_out
    gemm_kernel<1><<<dim3(2, 512), 256>>>(Wm[3], nullptr, nullptr, (float*)d_out);
}

// round 6
// speedup vs baseline: 1.5827x; 1.5827x over previous
#include <cuda_runtime.h>
#include <cstdint>

#define BB   16
#define TT   4096
#define CC   256
#define NCH  32
#define CLEN 128
#define NELEM (BB*TT*CC)
#define NAGG  (BB*NCH*CC)

__device__ float g_xs[NELEM];
__device__ float g_k [NELEM];
__device__ float g_v [NELEM];
__device__ float g_sr[NELEM];
__device__ float g_bA[NELEM], g_bB[NELEM], g_bP[NELEM];
__device__ float g_fA[NAGG], g_fB[NAGG], g_fP[NAGG];
__device__ float g_bAg[NAGG], g_bBg[NAGG], g_bPg[NAGG];
__device__ float g_pA[NAGG], g_pB[NAGG], g_pP[NAGG];
__device__ float g_sA[NAGG], g_sB[NAGG], g_sP[NAGG];
__device__ float g_wT[4 * 65536];   // transposed tf32-rounded weights [w][n][k]

__device__ __forceinline__ float f2tf(float x) {
    uint32_t r; asm("cvt.rna.tf32.f32 %0, %1;" : "=r"(r) : "f"(x));
    return __uint_as_float(r);
}

__device__ __forceinline__ void mma8(float* c, const uint32_t* a, const uint32_t* b) {
    asm volatile(
        "mma.sync.aligned.m16n8k8.row.col.f32.tf32.tf32.f32 "
        "{%0,%1,%2,%3}, {%4,%5,%6,%7}, {%8,%9}, {%0,%1,%2,%3};"
        : "+f"(c[0]), "+f"(c[1]), "+f"(c[2]), "+f"(c[3])
        : "r"(a[0]), "r"(a[1]), "r"(a[2]), "r"(a[3]), "r"(b[0]), "r"(b[1]));
}

template<int JM>
__device__ __forceinline__ int seqmap(int s) {
    return (JM == 0) ? s : (((s & 63) << 6) | (s >> 6));
}

// ---------------- omni_shift (output tf32-rounded) ---------------------------
__global__ __launch_bounds__(256) void omni_kernel(
    const float* __restrict__ x, const float* __restrict__ alpha,
    const float* __restrict__ w1, const float* __restrict__ w3,
    const float* __restrict__ w5)
{
    int c = threadIdx.x;
    int b = blockIdx.x >> 6;
    int w = blockIdx.x & 63;
    float a0 = alpha[0], a1 = alpha[1], a2 = alpha[2], a3 = alpha[3];

    float coef[5][5];
    #pragma unroll
    for (int r = 0; r < 5; r++)
        #pragma unroll
        for (int d = 0; d < 5; d++)
            coef[r][d] = a3 * w5[c * 25 + r * 5 + d];
    #pragma unroll
    for (int r = 0; r < 3; r++)
        #pragma unroll
        for (int d = 0; d < 3; d++)
            coef[r + 1][d + 1] += a2 * w3[c * 9 + r * 3 + d];
    coef[2][2] += a0 + a1 * w1[c];

    const float* xb = x + (size_t)b * TT * CC + c;
    float* ob = g_xs + (size_t)b * TT * CC + c;

    float win[5][5];
    #pragma unroll
    for (int r = 0; r < 5; r++) {
        int hr = r - 2;
        #pragma unroll
        for (int d = 0; d < 5; d++) {
            int wx = w + d - 2;
            win[r][d] = (hr >= 0 && wx >= 0 && wx < 64) ? xb[(hr * 64 + wx) * CC] : 0.0f;
        }
    }
    for (int h = 0; h < 64; h++) {
        float acc = 0.0f;
        #pragma unroll
        for (int r = 0; r < 5; r++)
            #pragma unroll
            for (int d = 0; d < 5; d++)
                acc = fmaf(coef[r][d], win[r][d], acc);
        ob[(h * 64 + w) * CC] = f2tf(acc);
        #pragma unroll
        for (int r = 0; r < 4; r++)
            #pragma unroll
            for (int d = 0; d < 5; d++)
                win[r][d] = win[r + 1][d];
        int hr = h + 3;
        #pragma unroll
        for (int d = 0; d < 5; d++) {
            int wx = w + d - 2;
            win[4][d] = (hr < 64 && wx >= 0 && wx < 64) ? xb[(hr * 64 + wx) * CC] : 0.0f;
        }
    }
}

// ---------------- weight transpose + tf32 round ------------------------------
__global__ void prep_kernel(const float* __restrict__ W0, const float* __restrict__ W1,
                            const float* __restrict__ W2, const float* __restrict__ W3)
{
    int widx = blockIdx.y;
    int n = blockIdx.x;
    int k = threadIdx.x;
    const float* W = (widx == 0) ? W0 : (widx == 1) ? W1 : (widx == 2) ? W2 : W3;
    g_wT[widx * 65536 + n * 256 + k] = f2tf(W[k * 256 + n]);
}

// ---------------- tf32 mma.sync GEMM: 128x128 tile, 8 warps (2x4), K-tile 32 --
// MODE 0: A=g_xs, bx 0..5 -> {Wk|Wv|Wr} halves -> g_k/g_v/g_sr (sigmoid on Wr)
// MODE 1: A=f2tf(g_sr*g_v), B=WoT, writes outp
template<int MODE>
__global__ __launch_bounds__(256) void gemm_mma(float* __restrict__ outp)
{
    __shared__ float As[128][36];
    __shared__ float Bs[128][36];

    int tid = threadIdx.x;
    int wid = tid >> 5, lane = tid & 31;
    int wm = wid & 1, wn = wid >> 1;      // warp tile 64x32 at (wm*64, wn*32)
    int qr = lane >> 2, qc = lane & 3;
    int bx = blockIdx.x, by = blockIdx.y;
    int m0 = by * 128;

    int widx, ncol0;
    float* Dst;
    bool sig = false;
    if (MODE == 0) {
        widx = bx >> 1;
        ncol0 = (bx & 1) * 128;
        Dst = (widx == 0) ? g_k : (widx == 1) ? g_v : g_sr;
        sig = (widx == 2);
    } else {
        widx = 3; ncol0 = bx * 128; Dst = outp;
    }
    const float* Bw = g_wT + widx * 65536;

    float acc[4][4][4];
    #pragma unroll
    for (int i = 0; i < 4; i++)
        #pragma unroll
        for (int j = 0; j < 4; j++)
            #pragma unroll
            for (int e = 0; e < 4; e++)
                acc[i][j][e] = 0.0f;

    for (int kt = 0; kt < 8; kt++) {
        int k0 = kt * 32;
        float4 afr[4], bfr[4];
        #pragma unroll
        for (int q = 0; q < 4; q++) {
            int id = tid + q * 256;           // 0..1023
            int r = id >> 3, f4 = (id & 7) * 4;
            size_t aidx = (size_t)(m0 + r) * CC + k0 + f4;
            if (MODE == 0) {
                afr[q] = *(const float4*)&g_xs[aidx];
            } else {
                float4 s4 = *(const float4*)&g_sr[aidx];
                float4 v4 = *(const float4*)&g_v[aidx];
                afr[q] = make_float4(f2tf(s4.x * v4.x), f2tf(s4.y * v4.y),
                                     f2tf(s4.z * v4.z), f2tf(s4.w * v4.w));
            }
            bfr[q] = *(const float4*)&Bw[(size_t)(ncol0 + r) * CC + k0 + f4];
        }
        __syncthreads();    // previous iteration's compute done
        #pragma unroll
        for (int q = 0; q < 4; q++) {
            int id = tid + q * 256;
            int r = id >> 3, f4 = (id & 7) * 4;
            *(float4*)&As[r][f4] = afr[q];
            *(float4*)&Bs[r][f4] = bfr[q];
        }
        __syncthreads();

        #pragma unroll
        for (int ks = 0; ks < 4; ks++) {
            int kk = ks * 8;
            uint32_t a[4][4], b[4][2];
            #pragma unroll
            for (int mf = 0; mf < 4; mf++) {
                int r = wm * 64 + mf * 16 + qr;
                a[mf][0] = __float_as_uint(As[r    ][kk + qc    ]);
                a[mf][1] = __float_as_uint(As[r + 8][kk + qc    ]);
                a[mf][2] = __float_as_uint(As[r    ][kk + qc + 4]);
                a[mf][3] = __float_as_uint(As[r + 8][kk + qc + 4]);
            }
            #pragma unroll
            for (int nf = 0; nf < 4; nf++) {
                int n = wn * 32 + nf * 8 + qr;
                b[nf][0] = __float_as_uint(Bs[n][kk + qc    ]);
                b[nf][1] = __float_as_uint(Bs[n][kk + qc + 4]);
            }
            #pragma unroll
            for (int mf = 0; mf < 4; mf++)
                #pragma unroll
                for (int nf = 0; nf < 4; nf++)
                    mma8(acc[mf][nf], a[mf], b[nf]);
        }
    }

    // epilogue: c0,c1 -> (row, col..col+1); c2,c3 -> (row+8, col..col+1)
    #pragma unroll
    for (int mf = 0; mf < 4; mf++) {
        int row = m0 + wm * 64 + mf * 16 + qr;
        #pragma unroll
        for (int nf = 0; nf < 4; nf++) {
            int col = ncol0 + wn * 32 + nf * 8 + qc * 2;
            float v0 = acc[mf][nf][0], v1 = acc[mf][nf][1];
            float v2 = acc[mf][nf][2], v3 = acc[mf][nf][3];
            if (sig) {
                v0 = 1.0f / (1.0f + __expf(-v0));
                v1 = 1.0f / (1.0f + __expf(-v1));
                v2 = 1.0f / (1.0f + __expf(-v2));
                v3 = 1.0f / (1.0f + __expf(-v3));
            }
            *(float2*)&Dst[(size_t)row * CC + col]       = make_float2(v0, v1);
            *(float2*)&Dst[(size_t)(row + 8) * CC + col] = make_float2(v2, v3);
        }
    }
}

// ---------------- scan phase 1 ----------------------------------------------
template<int JM>
__global__ __launch_bounds__(256) void scan_p1(const float* __restrict__ sd, int j)
{
    int c = threadIdx.x;
    int b = blockIdx.x >> 5;
    int ch = blockIdx.x & 31;
    float wneg = -__expf(sd[j * CC + c] * (1.0f / 4096.0f));
    int base = b * TT * CC + c;
    int s0 = ch * CLEN;

    float a = 0.0f, bb = 0.0f, p = -1e38f;
    #pragma unroll 4
    for (int i = 0; i < CLEN; i++) {
        int t = seqmap<JM>(s0 + i);
        float kt = g_k[base + t * CC];
        float vt = g_v[base + t * CC];
        float q = fmaxf(p + wneg, kt);
        float e1 = __expf(p + wneg - q);
        float e2 = __expf(kt - q);
        a = e1 * a + e2 * vt; bb = e1 * bb + e2; p = q;
    }
    int ai = (b * NCH + ch) * CC + c;
    g_fA[ai] = a; g_fB[ai] = bb; g_fP[ai] = p;

    a = 0.0f; bb = 0.0f; p = -1e38f;
    #pragma unroll 4
    for (int i = CLEN - 1; i >= 0; i--) {
        int s = s0 + i;
        int t = seqmap<JM>(s);
        float kt = g_k[base + t * CC];
        float vt = g_v[base + t * CC];
        int si = base + s * CC;
        g_bA[si] = a; g_bB[si] = bb; g_bP[si] = p;
        float q = fmaxf(p + wneg, kt);
        float e1 = __expf(p + wneg - q);
        float e2 = __expf(kt - q);
        a = e1 * a + e2 * vt; bb = e1 * bb + e2; p = q;
    }
    g_bAg[ai] = a; g_bBg[ai] = bb; g_bPg[ai] = p;
}

// ---------------- scan phase 2 (fwd/bwd split across blocks) -----------------
__global__ __launch_bounds__(256) void scan_p2(const float* __restrict__ sd, int j)
{
    int idx = blockIdx.x * 256 + threadIdx.x;   // 0..8191
    int dir = idx >> 12;
    int bc = idx & 4095;
    int b = bc >> 8, c = bc & 255;
    float wneg = -__expf(sd[j * CC + c] * (1.0f / 4096.0f));
    float dec = (float)CLEN * wneg;
    float a = 0.0f, bb = 0.0f, p = -1e38f;
    if (dir == 0) {
        for (int ch = 0; ch < NCH; ch++) {
            int ai = (b * NCH + ch) * CC + c;
            g_pA[ai] = a; g_pB[ai] = bb; g_pP[ai] = p;
            float Ag = g_fA[ai], Bg = g_fB[ai], Pg = g_fP[ai];
            float q = fmaxf(p + dec, Pg);
            float e1 = __expf(p + dec - q), e2 = __expf(Pg - q);
            a = e1 * a + e2 * Ag; bb = e1 * bb + e2 * Bg; p = q;
        }
    } else {
        for (int ch = NCH - 1; ch >= 0; ch--) {
            int ai = (b * NCH + ch) * CC + c;
            g_sA[ai] = a; g_sB[ai] = bb; g_sP[ai] = p;
            float Ag = g_bAg[ai], Bg = g_bBg[ai], Pg = g_bPg[ai];
            float q = fmaxf(Pg, p + dec);
            float e1 = __expf(Pg - q), e2 = __expf(p + dec - q);
            a = e1 * Ag + e2 * a; bb = e1 * Bg + e2 * bb; p = q;
        }
    }
}

// ---------------- scan phase 3 ----------------------------------------------
template<int JM>
__global__ __launch_bounds__(256) void scan_p3(
    const float* __restrict__ sd, const float* __restrict__ sf, int j)
{
    int c = threadIdx.x;
    int b = blockIdx.x >> 5;
    int ch = blockIdx.x & 31;
    float wneg = -__expf(sd[j * CC + c] * (1.0f / 4096.0f));
    float u = sf[j * CC + c] * (1.0f / 4096.0f);
    int base = b * TT * CC + c;
    int ai = (b * NCH + ch) * CC + c;

    float af = g_pA[ai], bf = g_pB[ai], pf = g_pP[ai];
    float As_ = g_sA[ai], Bs_ = g_sB[ai], Ps_ = g_sP[ai];
    int s0 = ch * CLEN;

    #pragma unroll 2
    for (int i = 0; i < CLEN; i++) {
        int s = s0 + i;
        int t = seqmap<JM>(s);
        int ti = base + t * CC;
        int si = base + s * CC;
        float kt = g_k[ti];
        float vt = g_v[ti];
        float al = g_bA[si], bl = g_bB[si], pl = g_bP[si];

        float dcy = Ps_ + (float)(CLEN - 1 - i) * wneg;
        float ps = u + kt;
        float q = fmaxf(fmaxf(pf, pl), fmaxf(dcy, ps));
        float ef = __expf(pf - q);
        float el = __expf(pl - q);
        float ed = __expf(dcy - q);
        float es = __expf(ps - q);
        float num = ef * af + el * al + ed * As_ + es * vt;
        float den = ef * bf + el * bl + ed * Bs_ + es;
        g_v[ti] = num / den;

        float qn = fmaxf(pf + wneg, kt);
        float e1 = __expf(pf + wneg - qn);
        float e2 = __expf(kt - qn);
        af = e1 * af + e2 * vt; bf = e1 * bf + e2; pf = qn;
    }
}

// ---------------- launcher ---------------------------------------------------
extern "C" void kernel_launch(void* const* d_in, const int* in_sizes, int n_in,
                              void* d_out, int out_size)
{
    const float *x = nullptr, *alpha = nullptr, *w1 = nullptr, *w3 = nullptr, *w5 = nullptr;
    const float* Wm[4] = {nullptr, nullptr, nullptr, nullptr};
    const float* S2[2] = {nullptr, nullptr};
    int nW = 0, nS = 0;
    for (int i = 0; i < n_in; i++) {
        int sz = in_sizes[i];
        const float* p = (const float*)d_in[i];
        if      (sz == NELEM) x = p;
        else if (sz == 4)     alpha = p;
        else if (sz == 256)   w1 = p;
        else if (sz == 2304)  w3 = p;
        else if (sz == 6400)  w5 = p;
        else if (sz == 65536) { if (nW < 4) Wm[nW++] = p; }
        else if (sz == 512)   { if (nS < 2) S2[nS++] = p; }
    }

    omni_kernel<<<BB * 64, 256>>>(x, alpha, w1, w3, w5);
    prep_kernel<<<dim3(256, 4), 256>>>(Wm[0], Wm[1], Wm[2], Wm[3]);

    gemm_mma<0><<<dim3(6, 512), 256>>>(nullptr);

    scan_p1<0><<<BB * NCH, 256>>>(S2[0], 0);
    scan_p2<<<32, 256>>>(S2[0], 0);
    scan_p3<0><<<BB * NCH, 256>>>(S2[0], S2[1], 0);

    scan_p1<1><<<BB * NCH, 256>>>(S2[0], 1);
    scan_p2<<<32, 256>>>(S2[0], 1);
    scan_p3<1><<<BB * NCH, 256>>>(S2[0], S2[1], 1);

    gemm_mma<1><<<dim3(2, 512), 256>>>((float*)d_out);
}

// round 7
// speedup vs baseline: 2.0895x; 1.3202x over previous
#include <cuda_runtime.h>
#include <cstdint>

#define BB   16
#define TT   4096
#define CC   256
#define NCH  256          // chunks per scan
#define CLEN 16           // T / NCH
#define SG   16           // supergroups (16 chunks each)
#define NELEM (BB*TT*CC)
#define NAGG  (BB*NCH*CC)
#define NSUP  (BB*SG*CC)

__device__ float g_xs[NELEM];
__device__ float g_k [NELEM];
__device__ float g_v [NELEM];
__device__ float g_sr[NELEM];
// chunk-level aggregates and intra-super exclusive prefixes/suffixes
__device__ float g_fA[NAGG], g_fB[NAGG], g_fP[NAGG];      // fwd chunk aggregates
__device__ float g_bAg[NAGG], g_bBg[NAGG], g_bPg[NAGG];   // bwd chunk aggregates
__device__ float g_pA[NAGG], g_pB[NAGG], g_pP[NAGG];      // intra-super fwd prefixes
__device__ float g_sA[NAGG], g_sB[NAGG], g_sP[NAGG];      // intra-super bwd suffixes
// super-level
__device__ float g_sgA[NSUP], g_sgB[NSUP], g_sgP[NSUP];   // fwd super aggregates
__device__ float g_sgbA[NSUP], g_sgbB[NSUP], g_sgbP[NSUP];// bwd super aggregates
__device__ float g_SPA[NSUP], g_SPB[NSUP], g_SPP[NSUP];   // fwd super exclusive prefixes
__device__ float g_SSA[NSUP], g_SSB[NSUP], g_SSP[NSUP];   // bwd super exclusive suffixes
__device__ float g_wT[4 * 65536];                         // transposed tf32 weights [w][n][k]

__device__ __forceinline__ float f2tf(float x) {
    uint32_t r; asm("cvt.rna.tf32.f32 %0, %1;" : "=r"(r) : "f"(x));
    return __uint_as_float(r);
}

__device__ __forceinline__ void mma8(float* c, const uint32_t* a, const uint32_t* b) {
    asm volatile(
        "mma.sync.aligned.m16n8k8.row.col.f32.tf32.tf32.f32 "
        "{%0,%1,%2,%3}, {%4,%5,%6,%7}, {%8,%9}, {%0,%1,%2,%3};"
        : "+f"(c[0]), "+f"(c[1]), "+f"(c[2]), "+f"(c[3])
        : "r"(a[0]), "r"(a[1]), "r"(a[2]), "r"(a[3]), "r"(b[0]), "r"(b[1]));
}

template<int JM>
__device__ __forceinline__ int seqmap(int s) {
    return (JM == 0) ? s : (((s & 63) << 6) | (s >> 6));
}

// ---------------- omni_shift (output tf32-rounded) ---------------------------
__global__ __launch_bounds__(256) void omni_kernel(
    const float* __restrict__ x, const float* __restrict__ alpha,
    const float* __restrict__ w1, const float* __restrict__ w3,
    const float* __restrict__ w5)
{
    int c = threadIdx.x;
    int b = blockIdx.x >> 6;
    int w = blockIdx.x & 63;
    float a0 = alpha[0], a1 = alpha[1], a2 = alpha[2], a3 = alpha[3];

    float coef[5][5];
    #pragma unroll
    for (int r = 0; r < 5; r++)
        #pragma unroll
        for (int d = 0; d < 5; d++)
            coef[r][d] = a3 * w5[c * 25 + r * 5 + d];
    #pragma unroll
    for (int r = 0; r < 3; r++)
        #pragma unroll
        for (int d = 0; d < 3; d++)
            coef[r + 1][d + 1] += a2 * w3[c * 9 + r * 3 + d];
    coef[2][2] += a0 + a1 * w1[c];

    const float* xb = x + (size_t)b * TT * CC + c;
    float* ob = g_xs + (size_t)b * TT * CC + c;

    float win[5][5];
    #pragma unroll
    for (int r = 0; r < 5; r++) {
        int hr = r - 2;
        #pragma unroll
        for (int d = 0; d < 5; d++) {
            int wx = w + d - 2;
            win[r][d] = (hr >= 0 && wx >= 0 && wx < 64) ? xb[(hr * 64 + wx) * CC] : 0.0f;
        }
    }
    for (int h = 0; h < 64; h++) {
        float acc = 0.0f;
        #pragma unroll
        for (int r = 0; r < 5; r++)
            #pragma unroll
            for (int d = 0; d < 5; d++)
                acc = fmaf(coef[r][d], win[r][d], acc);
        ob[(h * 64 + w) * CC] = f2tf(acc);
        #pragma unroll
        for (int r = 0; r < 4; r++)
            #pragma unroll
            for (int d = 0; d < 5; d++)
                win[r][d] = win[r + 1][d];
        int hr = h + 3;
        #pragma unroll
        for (int d = 0; d < 5; d++) {
            int wx = w + d - 2;
            win[4][d] = (hr < 64 && wx >= 0 && wx < 64) ? xb[(hr * 64 + wx) * CC] : 0.0f;
        }
    }
}

// ---------------- weight transpose + tf32 round ------------------------------
__global__ void prep_kernel(const float* __restrict__ W0, const float* __restrict__ W1,
                            const float* __restrict__ W2, const float* __restrict__ W3)
{
    int widx = blockIdx.y;
    int n = blockIdx.x;
    int k = threadIdx.x;
    const float* W = (widx == 0) ? W0 : (widx == 1) ? W1 : (widx == 2) ? W2 : W3;
    g_wT[widx * 65536 + n * 256 + k] = f2tf(W[k * 256 + n]);
}

// ---------------- tf32 mma.sync GEMM (unchanged from passing R6) -------------
template<int MODE>
__global__ __launch_bounds__(256) void gemm_mma(float* __restrict__ outp)
{
    __shared__ float As[128][36];
    __shared__ float Bs[128][36];

    int tid = threadIdx.x;
    int wid = tid >> 5, lane = tid & 31;
    int wm = wid & 1, wn = wid >> 1;
    int qr = lane >> 2, qc = lane & 3;
    int bx = blockIdx.x, by = blockIdx.y;
    int m0 = by * 128;

    int widx, ncol0;
    float* Dst;
    bool sig = false;
    if (MODE == 0) {
        widx = bx >> 1;
        ncol0 = (bx & 1) * 128;
        Dst = (widx == 0) ? g_k : (widx == 1) ? g_v : g_sr;
        sig = (widx == 2);
    } else {
        widx = 3; ncol0 = bx * 128; Dst = outp;
    }
    const float* Bw = g_wT + widx * 65536;

    float acc[4][4][4];
    #pragma unroll
    for (int i = 0; i < 4; i++)
        #pragma unroll
        for (int j = 0; j < 4; j++)
            #pragma unroll
            for (int e = 0; e < 4; e++)
                acc[i][j][e] = 0.0f;

    for (int kt = 0; kt < 8; kt++) {
        int k0 = kt * 32;
        float4 afr[4], bfr[4];
        #pragma unroll
        for (int q = 0; q < 4; q++) {
            int id = tid + q * 256;
            int r = id >> 3, f4 = (id & 7) * 4;
            size_t aidx = (size_t)(m0 + r) * CC + k0 + f4;
            if (MODE == 0) {
                afr[q] = *(const float4*)&g_xs[aidx];
            } else {
                float4 s4 = *(const float4*)&g_sr[aidx];
                float4 v4 = *(const float4*)&g_v[aidx];
                afr[q] = make_float4(f2tf(s4.x * v4.x), f2tf(s4.y * v4.y),
                                     f2tf(s4.z * v4.z), f2tf(s4.w * v4.w));
            }
            bfr[q] = *(const float4*)&Bw[(size_t)(ncol0 + r) * CC + k0 + f4];
        }
        __syncthreads();
        #pragma unroll
        for (int q = 0; q < 4; q++) {
            int id = tid + q * 256;
            int r = id >> 3, f4 = (id & 7) * 4;
            *(float4*)&As[r][f4] = afr[q];
            *(float4*)&Bs[r][f4] = bfr[q];
        }
        __syncthreads();

        #pragma unroll
        for (int ks = 0; ks < 4; ks++) {
            int kk = ks * 8;
            uint32_t a[4][4], b[4][2];
            #pragma unroll
            for (int mf = 0; mf < 4; mf++) {
                int r = wm * 64 + mf * 16 + qr;
                a[mf][0] = __float_as_uint(As[r    ][kk + qc    ]);
                a[mf][1] = __float_as_uint(As[r + 8][kk + qc    ]);
                a[mf][2] = __float_as_uint(As[r    ][kk + qc + 4]);
                a[mf][3] = __float_as_uint(As[r + 8][kk + qc + 4]);
            }
            #pragma unroll
            for (int nf = 0; nf < 4; nf++) {
                int n = wn * 32 + nf * 8 + qr;
                b[nf][0] = __float_as_uint(Bs[n][kk + qc    ]);
                b[nf][1] = __float_as_uint(Bs[n][kk + qc + 4]);
            }
            #pragma unroll
            for (int mf = 0; mf < 4; mf++)
                #pragma unroll
                for (int nf = 0; nf < 4; nf++)
                    mma8(acc[mf][nf], a[mf], b[nf]);
        }
    }

    #pragma unroll
    for (int mf = 0; mf < 4; mf++) {
        int row = m0 + wm * 64 + mf * 16 + qr;
        #pragma unroll
        for (int nf = 0; nf < 4; nf++) {
            int col = ncol0 + wn * 32 + nf * 8 + qc * 2;
            float v0 = acc[mf][nf][0], v1 = acc[mf][nf][1];
            float v2 = acc[mf][nf][2], v3 = acc[mf][nf][3];
            if (sig) {
                v0 = 1.0f / (1.0f + __expf(-v0));
                v1 = 1.0f / (1.0f + __expf(-v1));
                v2 = 1.0f / (1.0f + __expf(-v2));
                v3 = 1.0f / (1.0f + __expf(-v3));
            }
            *(float2*)&Dst[(size_t)row * CC + col]       = make_float2(v0, v1);
            *(float2*)&Dst[(size_t)(row + 8) * CC + col] = make_float2(v2, v3);
        }
    }
}

// ---------------- scan phase 1: chunk aggregates (k,v read once, in regs) ----
template<int JM>
__global__ __launch_bounds__(256, 2) void scan_p1(const float* __restrict__ sd, int j)
{
    int c = threadIdx.x;
    int b = blockIdx.x >> 8;
    int ch = blockIdx.x & 255;
    float wneg = -__expf(sd[j * CC + c] * (1.0f / 4096.0f));
    int base = b * TT * CC + c;
    int s0 = ch * CLEN;

    float kk[CLEN], vv[CLEN];
    #pragma unroll
    for (int i = 0; i < CLEN; i++) {
        int t = seqmap<JM>(s0 + i);
        kk[i] = g_k[base + t * CC];
        vv[i] = g_v[base + t * CC];
    }
    int ai = (b * NCH + ch) * CC + c;

    // forward aggregate (anchored at chunk end)
    float a = 0.0f, bb = 0.0f, p = -1e38f;
    #pragma unroll
    for (int i = 0; i < CLEN; i++) {
        float q = fmaxf(p + wneg, kk[i]);
        float e1 = __expf(p + wneg - q);
        float e2 = __expf(kk[i] - q);
        a = e1 * a + e2 * vv[i]; bb = e1 * bb + e2; p = q;
    }
    g_fA[ai] = a; g_fB[ai] = bb; g_fP[ai] = p;

    // backward aggregate (anchored at chunk start)
    a = 0.0f; bb = 0.0f; p = -1e38f;
    #pragma unroll
    for (int i = CLEN - 1; i >= 0; i--) {
        float q = fmaxf(p + wneg, kk[i]);
        float e1 = __expf(p + wneg - q);
        float e2 = __expf(kk[i] - q);
        a = e1 * a + e2 * vv[i]; bb = e1 * bb + e2; p = q;
    }
    g_bAg[ai] = a; g_bBg[ai] = bb; g_bPg[ai] = p;
}

// ---------------- scan phase 2a: intra-super prefixes/suffixes + super aggs --
__global__ __launch_bounds__(256) void scan_p2a(const float* __restrict__ sd, int j)
{
    int c = threadIdx.x;
    int bx = blockIdx.x;               // 512 blocks: dir(1) b(4) sg(4)
    int dir = bx >> 8;
    int b = (bx >> 4) & 15;
    int sg = bx & 15;
    float wneg = -__expf(sd[j * CC + c] * (1.0f / 4096.0f));
    float dec = (float)CLEN * wneg;
    int si = (b * SG + sg) * CC + c;
    float a = 0.0f, bb = 0.0f, p = -1e38f;

    if (dir == 0) {
        #pragma unroll
        for (int chl = 0; chl < 16; chl++) {
            int ai = (b * NCH + sg * 16 + chl) * CC + c;
            g_pA[ai] = a; g_pB[ai] = bb; g_pP[ai] = p;
            float Ag = g_fA[ai], Bg = g_fB[ai], Pg = g_fP[ai];
            float q = fmaxf(p + dec, Pg);
            float e1 = __expf(p + dec - q), e2 = __expf(Pg - q);
            a = e1 * a + e2 * Ag; bb = e1 * bb + e2 * Bg; p = q;
        }
        g_sgA[si] = a; g_sgB[si] = bb; g_sgP[si] = p;
    } else {
        #pragma unroll
        for (int chl = 15; chl >= 0; chl--) {
            int ai = (b * NCH + sg * 16 + chl) * CC + c;
            g_sA[ai] = a; g_sB[ai] = bb; g_sP[ai] = p;
            float Ag = g_bAg[ai], Bg = g_bBg[ai], Pg = g_bPg[ai];
            float q = fmaxf(Pg, p + dec);
            float e1 = __expf(Pg - q), e2 = __expf(p + dec - q);
            a = e1 * Ag + e2 * a; bb = e1 * Bg + e2 * bb; p = q;
        }
        g_sgbA[si] = a; g_sgbB[si] = bb; g_sgbP[si] = p;
    }
}

// ---------------- scan phase 2b: super-level exclusive scan ------------------
__global__ __launch_bounds__(256) void scan_p2b(const float* __restrict__ sd, int j)
{
    int idx = blockIdx.x * 256 + threadIdx.x;   // 0..8191: dir(1) b(4) c(8)
    int dir = idx >> 12;
    int b = (idx >> 8) & 15;
    int c = idx & 255;
    float wneg = -__expf(sd[j * CC + c] * (1.0f / 4096.0f));
    float dec = (float)(CLEN * 16) * wneg;      // 256 steps per super
    float a = 0.0f, bb = 0.0f, p = -1e38f;

    if (dir == 0) {
        #pragma unroll
        for (int sg = 0; sg < SG; sg++) {
            int si = (b * SG + sg) * CC + c;
            g_SPA[si] = a; g_SPB[si] = bb; g_SPP[si] = p;
            float Ag = g_sgA[si], Bg = g_sgB[si], Pg = g_sgP[si];
            float q = fmaxf(p + dec, Pg);
            float e1 = __expf(p + dec - q), e2 = __expf(Pg - q);
            a = e1 * a + e2 * Ag; bb = e1 * bb + e2 * Bg; p = q;
        }
    } else {
        #pragma unroll
        for (int sg = SG - 1; sg >= 0; sg--) {
            int si = (b * SG + sg) * CC + c;
            g_SSA[si] = a; g_SSB[si] = bb; g_SSP[si] = p;
            float Ag = g_sgbA[si], Bg = g_sgbB[si], Pg = g_sgbP[si];
            float q = fmaxf(Pg, p + dec);
            float e1 = __expf(Pg - q), e2 = __expf(p + dec - q);
            a = e1 * Ag + e2 * a; bb = e1 * Bg + e2 * bb; p = q;
        }
    }
}

// ---------------- scan phase 3: all-register chunk pass, writes v ------------
template<int JM>
__global__ __launch_bounds__(256, 1) void scan_p3(
    const float* __restrict__ sd, const float* __restrict__ sf, int j)
{
    int c = threadIdx.x;
    int b = blockIdx.x >> 8;
    int ch = blockIdx.x & 255;
    int sg = ch >> 4, chl = ch & 15;
    float wneg = -__expf(sd[j * CC + c] * (1.0f / 4096.0f));
    float u = sf[j * CC + c] * (1.0f / 4096.0f);
    int base = b * TT * CC + c;
    int ai = (b * NCH + ch) * CC + c;
    int si = (b * SG + sg) * CC + c;
    int s0 = ch * CLEN;

    // full fwd prefix = super prefix (shift chl*16 steps) ⊕ intra prefix
    float af, bf, pf;
    {
        float pa = g_pA[ai], pb = g_pB[ai], pp = g_pP[ai];
        float Sa = g_SPA[si], Sb = g_SPB[si], Sp = g_SPP[si];
        float sh = Sp + (float)(chl * CLEN) * wneg;
        float q = fmaxf(sh, pp);
        float e1 = __expf(sh - q), e2 = __expf(pp - q);
        af = e1 * Sa + e2 * pa; bf = e1 * Sb + e2 * pb; pf = q;
    }
    // full suffix = intra suffix ⊕ super suffix (shift (15-chl)*16 steps)
    float ab, bbv, pbw;
    {
        float sa = g_sA[ai], sb = g_sB[ai], sp = g_sP[ai];
        float Ta = g_SSA[si], Tb = g_SSB[si], Tp = g_SSP[si];
        float sh = Tp + (float)((15 - chl) * CLEN) * wneg;
        float q = fmaxf(sp, sh);
        float e1 = __expf(sp - q), e2 = __expf(sh - q);
        ab = e1 * sa + e2 * Ta; bbv = e1 * sb + e2 * Tb; pbw = q;
    }

    float kk[CLEN], vv[CLEN];
    #pragma unroll
    for (int i = 0; i < CLEN; i++) {
        int t = seqmap<JM>(s0 + i);
        kk[i] = g_k[base + t * CC];
        vv[i] = g_v[base + t * CC];
    }

    // forward pass: record pre-update fwd carries (anchored at s)
    float fA[CLEN], fB[CLEN], fP[CLEN];
    #pragma unroll
    for (int i = 0; i < CLEN; i++) {
        fA[i] = af; fB[i] = bf; fP[i] = pf;
        float q = fmaxf(pf + wneg, kk[i]);
        float e1 = __expf(pf + wneg - q);
        float e2 = __expf(kk[i] - q);
        af = e1 * af + e2 * vv[i]; bf = e1 * bf + e2; pf = q;
    }

    // backward pass: combine fwd + running bwd + self, then fold element in
    #pragma unroll
    for (int i = CLEN - 1; i >= 0; i--) {
        int t = seqmap<JM>(s0 + i);
        float ps = u + kk[i];
        float q = fmaxf(fmaxf(fP[i], pbw), ps);
        float ef = __expf(fP[i] - q);
        float eb = __expf(pbw - q);
        float es = __expf(ps - q);
        float num = ef * fA[i] + eb * ab + es * vv[i];
        float den = ef * fB[i] + eb * bbv + es;
        g_v[base + t * CC] = num / den;

        float qn = fmaxf(pbw + wneg, kk[i]);
        float e1 = __expf(pbw + wneg - qn);
        float e2 = __expf(kk[i] - qn);
        ab = e1 * ab + e2 * vv[i]; bbv = e1 * bbv + e2; pbw = qn;
    }
}

// ---------------- launcher ---------------------------------------------------
extern "C" void kernel_launch(void* const* d_in, const int* in_sizes, int n_in,
                              void* d_out, int out_size)
{
    const float *x = nullptr, *alpha = nullptr, *w1 = nullptr, *w3 = nullptr, *w5 = nullptr;
    const float* Wm[4] = {nullptr, nullptr, nullptr, nullptr};
    const float* S2[2] = {nullptr, nullptr};
    int nW = 0, nS = 0;
    for (int i = 0; i < n_in; i++) {
        int sz = in_sizes[i];
        const float* p = (const float*)d_in[i];
        if      (sz == NELEM) x = p;
        else if (sz == 4)     alpha = p;
        else if (sz == 256)   w1 = p;
        else if (sz == 2304)  w3 = p;
        else if (sz == 6400)  w5 = p;
        else if (sz == 65536) { if (nW < 4) Wm[nW++] = p; }
        else if (sz == 512)   { if (nS < 2) S2[nS++] = p; }
    }

    omni_kernel<<<BB * 64, 256>>>(x, alpha, w1, w3, w5);
    prep_kernel<<<dim3(256, 4), 256>>>(Wm[0], Wm[1], Wm[2], Wm[3]);

    gemm_mma<0><<<dim3(6, 512), 256>>>(nullptr);

    scan_p1<0><<<BB * NCH, 256>>>(S2[0], 0);
    scan_p2a<<<512, 256>>>(S2[0], 0);
    scan_p2b<<<32, 256>>>(S2[0], 0);
    scan_p3<0><<<BB * NCH, 256>>>(S2[0], S2[1], 0);

    scan_p1<1><<<BB * NCH, 256>>>(S2[0], 1);
    scan_p2a<<<512, 256>>>(S2[0], 1);
    scan_p2b<<<32, 256>>>(S2[0], 1);
    scan_p3<1><<<BB * NCH, 256>>>(S2[0], S2[1], 1);

    gemm_mma<1><<<dim3(2, 512), 256>>>((float*)d_out);
}

// round 9
// speedup vs baseline: 2.2230x; 1.0639x over previous
#include <cuda_runtime.h>
#include <cstdint>

#define BB   16
#define TT   4096
#define CC   256
#define NCH  256          // chunks per scan
#define CLEN 16           // T / NCH
#define SG   16           // supergroups (16 chunks each)
#define NELEM (BB*TT*CC)
#define NAGG  (BB*NCH*CC)
#define NSUP  (BB*SG*CC)

__device__ float g_xs[NELEM];
__device__ float g_k [NELEM];
__device__ float g_v [NELEM];
__device__ float g_sr[NELEM];
// chunk-level aggregates and intra-super exclusive prefixes/suffixes
__device__ float g_fA[NAGG], g_fB[NAGG], g_fP[NAGG];      // fwd chunk aggregates
__device__ float g_bAg[NAGG], g_bBg[NAGG], g_bPg[NAGG];   // bwd chunk aggregates
__device__ float g_pA[NAGG], g_pB[NAGG], g_pP[NAGG];      // intra-super fwd prefixes
__device__ float g_sA[NAGG], g_sB[NAGG], g_sP[NAGG];      // intra-super bwd suffixes
// super-level
__device__ float g_sgA[NSUP], g_sgB[NSUP], g_sgP[NSUP];   // fwd super aggregates
__device__ float g_sgbA[NSUP], g_sgbB[NSUP], g_sgbP[NSUP];// bwd super aggregates
__device__ float g_SPA[NSUP], g_SPB[NSUP], g_SPP[NSUP];   // fwd super exclusive prefixes
__device__ float g_SSA[NSUP], g_SSB[NSUP], g_SSP[NSUP];   // bwd super exclusive suffixes
__device__ float g_wT[4 * 65536];                         // transposed tf32 weights [w][n][k]

__device__ __forceinline__ float f2tf(float x) {
    uint32_t r; asm("cvt.rna.tf32.f32 %0, %1;" : "=r"(r) : "f"(x));
    return __uint_as_float(r);
}

__device__ __forceinline__ void mma8(float* c, const uint32_t* a, const uint32_t* b) {
    asm volatile(
        "mma.sync.aligned.m16n8k8.row.col.f32.tf32.tf32.f32 "
        "{%0,%1,%2,%3}, {%4,%5,%6,%7}, {%8,%9}, {%0,%1,%2,%3};"
        : "+f"(c[0]), "+f"(c[1]), "+f"(c[2]), "+f"(c[3])
        : "r"(a[0]), "r"(a[1]), "r"(a[2]), "r"(a[3]), "r"(b[0]), "r"(b[1]));
}

__device__ __forceinline__ void cpa16(uint32_t saddr, const void* gaddr) {
    asm volatile("cp.async.cg.shared.global [%0], [%1], 16;"
                 :: "r"(saddr), "l"(gaddr) : "memory");
}
#define CP_COMMIT() asm volatile("cp.async.commit_group;" ::: "memory")
#define CP_WAIT1()  asm volatile("cp.async.wait_group 1;" ::: "memory")
#define CP_WAIT0()  asm volatile("cp.async.wait_group 0;" ::: "memory")

template<int JM>
__device__ __forceinline__ int seqmap(int s) {
    return (JM == 0) ? s : (((s & 63) << 6) | (s >> 6));
}

// ---------------- omni_shift (output tf32-rounded) ---------------------------
__global__ __launch_bounds__(256) void omni_kernel(
    const float* __restrict__ x, const float* __restrict__ alpha,
    const float* __restrict__ w1, const float* __restrict__ w3,
    const float* __restrict__ w5)
{
    int c = threadIdx.x;
    int b = blockIdx.x >> 6;
    int w = blockIdx.x & 63;
    float a0 = alpha[0], a1 = alpha[1], a2 = alpha[2], a3 = alpha[3];

    float coef[5][5];
    #pragma unroll
    for (int r = 0; r < 5; r++)
        #pragma unroll
        for (int d = 0; d < 5; d++)
            coef[r][d] = a3 * w5[c * 25 + r * 5 + d];
    #pragma unroll
    for (int r = 0; r < 3; r++)
        #pragma unroll
        for (int d = 0; d < 3; d++)
            coef[r + 1][d + 1] += a2 * w3[c * 9 + r * 3 + d];
    coef[2][2] += a0 + a1 * w1[c];

    const float* xb = x + (size_t)b * TT * CC + c;
    float* ob = g_xs + (size_t)b * TT * CC + c;

    float win[5][5];
    #pragma unroll
    for (int r = 0; r < 5; r++) {
        int hr = r - 2;
        #pragma unroll
        for (int d = 0; d < 5; d++) {
            int wx = w + d - 2;
            win[r][d] = (hr >= 0 && wx >= 0 && wx < 64) ? xb[(hr * 64 + wx) * CC] : 0.0f;
        }
    }
    for (int h = 0; h < 64; h++) {
        float acc = 0.0f;
        #pragma unroll
        for (int r = 0; r < 5; r++)
            #pragma unroll
            for (int d = 0; d < 5; d++)
                acc = fmaf(coef[r][d], win[r][d], acc);
        ob[(h * 64 + w) * CC] = f2tf(acc);
        #pragma unroll
        for (int r = 0; r < 4; r++)
            #pragma unroll
            for (int d = 0; d < 5; d++)
                win[r][d] = win[r + 1][d];
        int hr = h + 3;
        #pragma unroll
        for (int d = 0; d < 5; d++) {
            int wx = w + d - 2;
            win[4][d] = (hr < 64 && wx >= 0 && wx < 64) ? xb[(hr * 64 + wx) * CC] : 0.0f;
        }
    }
}

// ---------------- weight transpose + tf32 round ------------------------------
__global__ void prep_kernel(const float* __restrict__ W0, const float* __restrict__ W1,
                            const float* __restrict__ W2, const float* __restrict__ W3)
{
    int widx = blockIdx.y;
    int n = blockIdx.x;
    int k = threadIdx.x;
    const float* W = (widx == 0) ? W0 : (widx == 1) ? W1 : (widx == 2) ? W2 : W3;
    g_wT[widx * 65536 + n * 256 + k] = f2tf(W[k * 256 + n]);
}

// ---------------- tf32 mma.sync GEMM, cp.async 2-stage pipeline --------------
// smem layout (floats): A stage0 [0,4608) A stage1 [4608,9216)
//                       B stage0 [9216,13824) B stage1 [13824,18432)
// tile row stride = 36 floats (pad).
template<int MODE>
__global__ __launch_bounds__(256) void gemm_mma(float* __restrict__ outp)
{
    extern __shared__ float sm[];

    int tid = threadIdx.x;
    int wid = tid >> 5, lane = tid & 31;
    int wm = wid & 1, wn = wid >> 1;
    int qr = lane >> 2, qc = lane & 3;
    int bx = blockIdx.x, by = blockIdx.y;
    int m0 = by * 128;

    int widx, ncol0;
    float* Dst;
    bool sig = false;
    if (MODE == 0) {
        widx = bx >> 1;
        ncol0 = (bx & 1) * 128;
        Dst = (widx == 0) ? g_k : (widx == 1) ? g_v : g_sr;
        sig = (widx == 2);
    } else {
        widx = 3; ncol0 = bx * 128; Dst = outp;
    }
    const float* Bw = g_wT + widx * 65536;

    // per-thread copy slots: id = tid + q*256 -> row id>>3, float4 col (id&7)
    int crow[4], ccol[4];
    uint32_t sAaddr[4], sBaddr[4];
    #pragma unroll
    for (int q = 0; q < 4; q++) {
        int id = tid + q * 256;
        crow[q] = id >> 3;
        ccol[q] = (id & 7) * 4;
        sAaddr[q] = (uint32_t)__cvta_generic_to_shared(&sm[crow[q] * 36 + ccol[q]]);
        sBaddr[q] = (uint32_t)__cvta_generic_to_shared(&sm[9216 + crow[q] * 36 + ccol[q]]);
    }

    float acc[4][4][4];
    #pragma unroll
    for (int i = 0; i < 4; i++)
        #pragma unroll
        for (int j = 0; j < 4; j++)
            #pragma unroll
            for (int e = 0; e < 4; e++)
                acc[i][j][e] = 0.0f;

    // issue loads for k-tile kt into stage st
    auto issue = [&](int kt, int st) {
        int k0 = kt * 32;
        uint32_t so = st * 4608 * 4;   // byte offset between stages
        #pragma unroll
        for (int q = 0; q < 4; q++) {
            cpa16(sBaddr[q] + so, &Bw[(size_t)(ncol0 + crow[q]) * CC + k0 + ccol[q]]);
            if (MODE == 0) {
                cpa16(sAaddr[q] + so, &g_xs[(size_t)(m0 + crow[q]) * CC + k0 + ccol[q]]);
            } else {
                size_t gi = (size_t)(m0 + crow[q]) * CC + k0 + ccol[q];
                float4 s4 = *(const float4*)&g_sr[gi];
                float4 v4 = *(const float4*)&g_v[gi];
                float4 av = make_float4(f2tf(s4.x * v4.x), f2tf(s4.y * v4.y),
                                        f2tf(s4.z * v4.z), f2tf(s4.w * v4.w));
                *(float4*)&sm[st * 4608 + crow[q] * 36 + ccol[q]] = av;
            }
        }
    };

    issue(0, 0);
    CP_COMMIT();

    for (int kt = 0; kt < 8; kt++) {
        int st = kt & 1;
        if (kt + 1 < 8) { issue(kt + 1, st ^ 1); CP_COMMIT(); CP_WAIT1(); }
        else            { CP_WAIT0(); }
        __syncthreads();

        const float* Ab = sm + st * 4608;
        const float* Bb = sm + 9216 + st * 4608;
        #pragma unroll
        for (int ks = 0; ks < 4; ks++) {
            int kk = ks * 8;
            uint32_t a[4][4], b[4][2];
            #pragma unroll
            for (int mf = 0; mf < 4; mf++) {
                int r = wm * 64 + mf * 16 + qr;
                a[mf][0] = __float_as_uint(Ab[r * 36       + kk + qc    ]);
                a[mf][1] = __float_as_uint(Ab[(r + 8) * 36 + kk + qc    ]);
                a[mf][2] = __float_as_uint(Ab[r * 36       + kk + qc + 4]);
                a[mf][3] = __float_as_uint(Ab[(r + 8) * 36 + kk + qc + 4]);
            }
            #pragma unroll
            for (int nf = 0; nf < 4; nf++) {
                int n = wn * 32 + nf * 8 + qr;
                b[nf][0] = __float_as_uint(Bb[n * 36 + kk + qc    ]);
                b[nf][1] = __float_as_uint(Bb[n * 36 + kk + qc + 4]);
            }
            #pragma unroll
            for (int mf = 0; mf < 4; mf++)
                #pragma unroll
                for (int nf = 0; nf < 4; nf++)
                    mma8(acc[mf][nf], a[mf], b[nf]);
        }
        __syncthreads();
    }

    #pragma unroll
    for (int mf = 0; mf < 4; mf++) {
        int row = m0 + wm * 64 + mf * 16 + qr;
        #pragma unroll
        for (int nf = 0; nf < 4; nf++) {
            int col = ncol0 + wn * 32 + nf * 8 + qc * 2;
            float v0 = acc[mf][nf][0], v1 = acc[mf][nf][1];
            float v2 = acc[mf][nf][2], v3 = acc[mf][nf][3];
            if (sig) {
                v0 = 1.0f / (1.0f + __expf(-v0));
                v1 = 1.0f / (1.0f + __expf(-v1));
                v2 = 1.0f / (1.0f + __expf(-v2));
                v3 = 1.0f / (1.0f + __expf(-v3));
            }
            *(float2*)&Dst[(size_t)row * CC + col]       = make_float2(v0, v1);
            *(float2*)&Dst[(size_t)(row + 8) * CC + col] = make_float2(v2, v3);
        }
    }
}

// ---------------- scan phase 1: chunk aggregates (k,v read once, in regs) ----
template<int JM>
__global__ __launch_bounds__(256, 2) void scan_p1(const float* __restrict__ sd, int j)
{
    int c = threadIdx.x;
    int b = blockIdx.x >> 8;
    int ch = blockIdx.x & 255;
    float wneg = -__expf(sd[j * CC + c] * (1.0f / 4096.0f));
    int base = b * TT * CC + c;
    int s0 = ch * CLEN;

    float kk[CLEN], vv[CLEN];
    #pragma unroll
    for (int i = 0; i < CLEN; i++) {
        int t = seqmap<JM>(s0 + i);
        kk[i] = g_k[base + t * CC];
        vv[i] = g_v[base + t * CC];
    }
    int ai = (b * NCH + ch) * CC + c;

    float a = 0.0f, bb = 0.0f, p = -1e38f;
    #pragma unroll
    for (int i = 0; i < CLEN; i++) {
        float q = fmaxf(p + wneg, kk[i]);
        float e1 = __expf(p + wneg - q);
        float e2 = __expf(kk[i] - q);
        a = e1 * a + e2 * vv[i]; bb = e1 * bb + e2; p = q;
    }
    g_fA[ai] = a; g_fB[ai] = bb; g_fP[ai] = p;

    a = 0.0f; bb = 0.0f; p = -1e38f;
    #pragma unroll
    for (int i = CLEN - 1; i >= 0; i--) {
        float q = fmaxf(p + wneg, kk[i]);
        float e1 = __expf(p + wneg - q);
        float e2 = __expf(kk[i] - q);
        a = e1 * a + e2 * vv[i]; bb = e1 * bb + e2; p = q;
    }
    g_bAg[ai] = a; g_bBg[ai] = bb; g_bPg[ai] = p;
}

// ---------------- scan phase 2a: intra-super prefixes/suffixes + super aggs --
__global__ __launch_bounds__(256) void scan_p2a(const float* __restrict__ sd, int j)
{
    int c = threadIdx.x;
    int bx = blockIdx.x;               // 512 blocks: dir(1) b(4) sg(4)
    int dir = bx >> 8;
    int b = (bx >> 4) & 15;
    int sg = bx & 15;
    float wneg = -__expf(sd[j * CC + c] * (1.0f / 4096.0f));
    float dec = (float)CLEN * wneg;
    int si = (b * SG + sg) * CC + c;
    float a = 0.0f, bb = 0.0f, p = -1e38f;

    if (dir == 0) {
        #pragma unroll
        for (int chl = 0; chl < 16; chl++) {
            int ai = (b * NCH + sg * 16 + chl) * CC + c;
            g_pA[ai] = a; g_pB[ai] = bb; g_pP[ai] = p;
            float Ag = g_fA[ai], Bg = g_fB[ai], Pg = g_fP[ai];
            float q = fmaxf(p + dec, Pg);
            float e1 = __expf(p + dec - q), e2 = __expf(Pg - q);
            a = e1 * a + e2 * Ag; bb = e1 * bb + e2 * Bg; p = q;
        }
        g_sgA[si] = a; g_sgB[si] = bb; g_sgP[si] = p;
    } else {
        #pragma unroll
        for (int chl = 15; chl >= 0; chl--) {
            int ai = (b * NCH + sg * 16 + chl) * CC + c;
            g_sA[ai] = a; g_sB[ai] = bb; g_sP[ai] = p;
            float Ag = g_bAg[ai], Bg = g_bBg[ai], Pg = g_bPg[ai];
            float q = fmaxf(Pg, p + dec);
            float e1 = __expf(Pg - q), e2 = __expf(p + dec - q);
            a = e1 * Ag + e2 * a; bb = e1 * Bg + e2 * bb; p = q;
        }
        g_sgbA[si] = a; g_sgbB[si] = bb; g_sgbP[si] = p;
    }
}

// ---------------- scan phase 2b: super-level exclusive scan ------------------
__global__ __launch_bounds__(256) void scan_p2b(const float* __restrict__ sd, int j)
{
    int idx = blockIdx.x * 256 + threadIdx.x;   // 0..8191: dir(1) b(4) c(8)
    int dir = idx >> 12;
    int b = (idx >> 8) & 15;
    int c = idx & 255;
    float wneg = -__expf(sd[j * CC + c] * (1.0f / 4096.0f));
    float dec = (float)(CLEN * 16) * wneg;      // 256 steps per super
    float a = 0.0f, bb = 0.0f, p = -1e38f;

    if (dir == 0) {
        #pragma unroll
        for (int sg = 0; sg < SG; sg++) {
            int si = (b * SG + sg) * CC + c;
            g_SPA[si] = a; g_SPB[si] = bb; g_SPP[si] = p;
            float Ag = g_sgA[si], Bg = g_sgB[si], Pg = g_sgP[si];
            float q = fmaxf(p + dec, Pg);
            float e1 = __expf(p + dec - q), e2 = __expf(Pg - q);
            a = e1 * a + e2 * Ag; bb = e1 * bb + e2 * Bg; p = q;
        }
    } else {
        #pragma unroll
        for (int sg = SG - 1; sg >= 0; sg--) {
            int si = (b * SG + sg) * CC + c;
            g_SSA[si] = a; g_SSB[si] = bb; g_SSP[si] = p;
            float Ag = g_sgbA[si], Bg = g_sgbB[si], Pg = g_sgbP[si];
            float q = fmaxf(Pg, p + dec);
            float e1 = __expf(Pg - q), e2 = __expf(p + dec - q);
            a = e1 * Ag + e2 * a; bb = e1 * Bg + e2 * bb; p = q;
        }
    }
}

// ---------------- scan phase 3: fwd states staged in smem, writes v ----------
template<int JM>
__global__ __launch_bounds__(256) void scan_p3(
    const float* __restrict__ sd, const float* __restrict__ sf, int j)
{
    __shared__ float shA[CLEN][256];
    __shared__ float shB[CLEN][256];

    int c = threadIdx.x;
    int b = blockIdx.x >> 8;
    int ch = blockIdx.x & 255;
    int sg = ch >> 4, chl = ch & 15;
    float wneg = -__expf(sd[j * CC + c] * (1.0f / 4096.0f));
    float u = sf[j * CC + c] * (1.0f / 4096.0f);
    int base = b * TT * CC + c;
    int ai = (b * NCH + ch) * CC + c;
    int si = (b * SG + sg) * CC + c;
    int s0 = ch * CLEN;

    // full fwd prefix = super prefix (shift chl*16 steps) ⊕ intra prefix
    float af, bf, pf;
    {
        float pa = g_pA[ai], pb = g_pB[ai], pp = g_pP[ai];
        float Sa = g_SPA[si], Sb = g_SPB[si], Sp = g_SPP[si];
        float sh = Sp + (float)(chl * CLEN) * wneg;
        float q = fmaxf(sh, pp);
        float e1 = __expf(sh - q), e2 = __expf(pp - q);
        af = e1 * Sa + e2 * pa; bf = e1 * Sb + e2 * pb; pf = q;
    }
    // full suffix = intra suffix ⊕ super suffix (shift (15-chl)*16 steps)
    float ab, bbv, pbw;
    {
        float sa = g_sA[ai], sb = g_sB[ai], sp = g_sP[ai];
        float Ta = g_SSA[si], Tb = g_SSB[si], Tp = g_SSP[si];
        float sh = Tp + (float)((15 - chl) * CLEN) * wneg;
        float q = fmaxf(sp, sh);
        float e1 = __expf(sp - q), e2 = __expf(sh - q);
        ab = e1 * sa + e2 * Ta; bbv = e1 * sb + e2 * Tb; pbw = q;
    }

    float kk[CLEN], vv[CLEN];
    #pragma unroll
    for (int i = 0; i < CLEN; i++) {
        int t = seqmap<JM>(s0 + i);
        kk[i] = g_k[base + t * CC];
        vv[i] = g_v[base + t * CC];
    }

    // forward pass: record pre-update fwd carries (A,B in smem, P in regs)
    float fP[CLEN];
    #pragma unroll
    for (int i = 0; i < CLEN; i++) {
        shA[i][c] = af; shB[i][c] = bf; fP[i] = pf;
        float q = fmaxf(pf + wneg, kk[i]);
        float e1 = __expf(pf + wneg - q);
        float e2 = __expf(kk[i] - q);
        af = e1 * af + e2 * vv[i]; bf = e1 * bf + e2; pf = q;
    }

    // backward pass: combine fwd + running bwd + self, then fold element in
    #pragma unroll
    for (int i = CLEN - 1; i >= 0; i--) {
        int t = seqmap<JM>(s0 + i);
        float ps = u + kk[i];
        float q = fmaxf(fmaxf(fP[i], pbw), ps);
        float ef = __expf(fP[i] - q);
        float eb = __expf(pbw - q);
        float es = __expf(ps - q);
        float num = ef * shA[i][c] + eb * ab + es * vv[i];
        float den = ef * shB[i][c] + eb * bbv + es;
        g_v[base + t * CC] = num / den;

        float qn = fmaxf(pbw + wneg, kk[i]);
        float e1 = __expf(pbw + wneg - qn);
        float e2 = __expf(kk[i] - qn);
        ab = e1 * ab + e2 * vv[i]; bbv = e1 * bbv + e2; pbw = qn;
    }
}

// ---------------- launcher ---------------------------------------------------
extern "C" void kernel_launch(void* const* d_in, const int* in_sizes, int n_in,
                              void* d_out, int out_size)
{
    const float *x = nullptr, *alpha = nullptr, *w1 = nullptr, *w3 = nullptr, *w5 = nullptr;
    const float* Wm[4] = {nullptr, nullptr, nullptr, nullptr};
    const float* S2[2] = {nullptr, nullptr};
    int nW = 0, nS = 0;
    for (int i = 0; i < n_in; i++) {
        int sz = in_sizes[i];
        const float* p = (const float*)d_in[i];
        if      (sz == NELEM) x = p;
        else if (sz == 4)     alpha = p;
        else if (sz == 256)   w1 = p;
        else if (sz == 2304)  w3 = p;
        else if (sz == 6400)  w5 = p;
        else if (sz == 65536) { if (nW < 4) Wm[nW++] = p; }
        else if (sz == 512)   { if (nS < 2) S2[nS++] = p; }
    }

    const int GSMEM = 18432 * 4;   // 73,728 B: 2-stage A+B tiles
    cudaFuncSetAttribute(gemm_mma<0>, cudaFuncAttributeMaxDynamicSharedMemorySize, GSMEM);
    cudaFuncSetAttribute(gemm_mma<1>, cudaFuncAttributeMaxDynamicSharedMemorySize, GSMEM);

    omni_kernel<<<BB * 64, 256>>>(x, alpha, w1, w3, w5);
    prep_kernel<<<dim3(256, 4), 256>>>(Wm[0], Wm[1], Wm[2], Wm[3]);

    gemm_mma<0><<<dim3(6, 512), 256, GSMEM>>>(nullptr);

    scan_p1<0><<<BB * NCH, 256>>>(S2[0], 0);
    scan_p2a<<<512, 256>>>(S2[0], 0);
    scan_p2b<<<32, 256>>>(S2[0], 0);
    scan_p3<0><<<BB * NCH, 256>>>(S2[0], S2[1], 0);

    scan_p1<1><<<BB * NCH, 256>>>(S2[0], 1);
    scan_p2a<<<512, 256>>>(S2[0], 1);
    scan_p2b<<<32, 256>>>(S2[0], 1);
    scan_p3<1><<<BB * NCH, 256>>>(S2[0], S2[1], 1);

    gemm_mma<1><<<dim3(2, 512), 256, GSMEM>>>((float*)d_out);
}

// round 10
// speedup vs baseline: 2.5058x; 1.1272x over previous
#include <cuda_runtime.h>
#include <cuda_fp16.h>
#include <cstdint>

#define BB   16
#define TT   4096
#define CC   256
#define NCH  256          // chunks per scan
#define CLEN 16           // T / NCH
#define SG   16           // supergroups (16 chunks each)
#define NELEM (BB*TT*CC)
#define NAGG  (BB*NCH*CC)
#define NSUP  (BB*SG*CC)

__device__ __half g_xsh[NELEM];    // omni output, fp16 (GEMM0 A)
__device__ __half g_pv [NELEM];    // fused sr*v product, fp16 (GEMM1 A)
__device__ __half g_whT[4 * 65536];// transposed fp16 weights [w][n][k]
__device__ float g_k [NELEM];
__device__ float g_v [NELEM];
__device__ float g_sr[NELEM];
// chunk-level aggregates and intra-super exclusive prefixes/suffixes
__device__ float g_fA[NAGG], g_fB[NAGG], g_fP[NAGG];
__device__ float g_bAg[NAGG], g_bBg[NAGG], g_bPg[NAGG];
__device__ float g_pA[NAGG], g_pB[NAGG], g_pP[NAGG];
__device__ float g_sA[NAGG], g_sB[NAGG], g_sP[NAGG];
// super-level
__device__ float g_sgA[NSUP], g_sgB[NSUP], g_sgP[NSUP];
__device__ float g_sgbA[NSUP], g_sgbB[NSUP], g_sgbP[NSUP];
__device__ float g_SPA[NSUP], g_SPB[NSUP], g_SPP[NSUP];
__device__ float g_SSA[NSUP], g_SSB[NSUP], g_SSP[NSUP];

__device__ __forceinline__ void mma16(float* c, const uint32_t* a, const uint32_t* b) {
    asm volatile(
        "mma.sync.aligned.m16n8k16.row.col.f32.f16.f16.f32 "
        "{%0,%1,%2,%3}, {%4,%5,%6,%7}, {%8,%9}, {%0,%1,%2,%3};"
        : "+f"(c[0]), "+f"(c[1]), "+f"(c[2]), "+f"(c[3])
        : "r"(a[0]), "r"(a[1]), "r"(a[2]), "r"(a[3]), "r"(b[0]), "r"(b[1]));
}

__device__ __forceinline__ void cpa16(uint32_t saddr, const void* gaddr) {
    asm volatile("cp.async.cg.shared.global [%0], [%1], 16;"
                 :: "r"(saddr), "l"(gaddr) : "memory");
}
#define CP_COMMIT() asm volatile("cp.async.commit_group;" ::: "memory")
#define CP_WAIT1()  asm volatile("cp.async.wait_group 1;" ::: "memory")
#define CP_WAIT0()  asm volatile("cp.async.wait_group 0;" ::: "memory")

template<int JM>
__device__ __forceinline__ int seqmap(int s) {
    return (JM == 0) ? s : (((s & 63) << 6) | (s >> 6));
}

// single-exp scan step: q = max(p+sh, kt); e1 = exp(p+sh-q); e2 = exp(kt-q)
// one of e1,e2 is 1 -> compute exp(-|d|) once.
__device__ __forceinline__ void step1(float& a, float& b, float& p,
                                      float sh, float kt, float vt) {
    float d = p + sh - kt;
    float e = __expf(-fabsf(d));
    bool gt = d > 0.0f;
    float e1 = gt ? 1.0f : e;
    float e2 = gt ? e : 1.0f;
    a = e1 * a + e2 * vt;
    b = e1 * b + e2;
    p = gt ? (p + sh) : kt;
}
// combine-variant: incoming aggregate (Ag,Bg,Pg) folded into carry (a,b,p)
__device__ __forceinline__ void stepagg(float& a, float& b, float& p, float sh,
                                        float Ag, float Bg, float Pg) {
    float d = p + sh - Pg;
    float e = __expf(-fabsf(d));
    bool gt = d > 0.0f;
    float e1 = gt ? 1.0f : e;
    float e2 = gt ? e : 1.0f;
    a = e1 * a + e2 * Ag;
    b = e1 * b + e2 * Bg;
    p = gt ? (p + sh) : Pg;
}

// ---------------- omni_shift (fp16 output) -----------------------------------
__global__ __launch_bounds__(256) void omni_kernel(
    const float* __restrict__ x, const float* __restrict__ alpha,
    const float* __restrict__ w1, const float* __restrict__ w3,
    const float* __restrict__ w5)
{
    int c = threadIdx.x;
    int b = blockIdx.x >> 6;
    int w = blockIdx.x & 63;
    float a0 = alpha[0], a1 = alpha[1], a2 = alpha[2], a3 = alpha[3];

    float coef[5][5];
    #pragma unroll
    for (int r = 0; r < 5; r++)
        #pragma unroll
        for (int d = 0; d < 5; d++)
            coef[r][d] = a3 * w5[c * 25 + r * 5 + d];
    #pragma unroll
    for (int r = 0; r < 3; r++)
        #pragma unroll
        for (int d = 0; d < 3; d++)
            coef[r + 1][d + 1] += a2 * w3[c * 9 + r * 3 + d];
    coef[2][2] += a0 + a1 * w1[c];

    const float* xb = x + (size_t)b * TT * CC + c;
    __half* ob = g_xsh + (size_t)b * TT * CC + c;

    float win[5][5];
    #pragma unroll
    for (int r = 0; r < 5; r++) {
        int hr = r - 2;
        #pragma unroll
        for (int d = 0; d < 5; d++) {
            int wx = w + d - 2;
            win[r][d] = (hr >= 0 && wx >= 0 && wx < 64) ? xb[(hr * 64 + wx) * CC] : 0.0f;
        }
    }
    for (int h = 0; h < 64; h++) {
        float acc = 0.0f;
        #pragma unroll
        for (int r = 0; r < 5; r++)
            #pragma unroll
            for (int d = 0; d < 5; d++)
                acc = fmaf(coef[r][d], win[r][d], acc);
        ob[(h * 64 + w) * CC] = __float2half_rn(acc);
        #pragma unroll
        for (int r = 0; r < 4; r++)
            #pragma unroll
            for (int d = 0; d < 5; d++)
                win[r][d] = win[r + 1][d];
        int hr = h + 3;
        #pragma unroll
        for (int d = 0; d < 5; d++) {
            int wx = w + d - 2;
            win[4][d] = (hr < 64 && wx >= 0 && wx < 64) ? xb[(hr * 64 + wx) * CC] : 0.0f;
        }
    }
}

// ---------------- weight transpose + fp16 round ------------------------------
__global__ void prep_kernel(const float* __restrict__ W0, const float* __restrict__ W1,
                            const float* __restrict__ W2, const float* __restrict__ W3)
{
    int widx = blockIdx.y;
    int n = blockIdx.x;
    int k = threadIdx.x;
    const float* W = (widx == 0) ? W0 : (widx == 1) ? W1 : (widx == 2) ? W2 : W3;
    g_whT[widx * 65536 + n * 256 + k] = __float2half_rn(W[k * 256 + n]);
}

// ---------------- fp16 mma.sync GEMM, cp.async 2-stage pipeline --------------
// K-tiles of 64 halves (128B rows). smem (halves, row stride 72 = 144B):
//   A st0 [0,9216) A st1 [9216,18432) B st0 [18432,27648) B st1 [27648,36864)
// MODE 0: A=g_xsh, bx 0..5 -> {Wk|Wv|Wr} halves -> g_k/g_v/g_sr (sigmoid on Wr)
// MODE 1: A=g_pv, B=WoT, writes outp, bx 0..1
template<int MODE>
__global__ __launch_bounds__(256) void gemm_mma(float* __restrict__ outp)
{
    extern __shared__ __half smh[];

    int tid = threadIdx.x;
    int wid = tid >> 5, lane = tid & 31;
    int wm = wid & 1, wn = wid >> 1;
    int qr = lane >> 2, qc = lane & 3;
    int bx = blockIdx.x, by = blockIdx.y;
    int m0 = by * 128;

    int widx, ncol0;
    float* Dst;
    bool sig = false;
    if (MODE == 0) {
        widx = bx >> 1;
        ncol0 = (bx & 1) * 128;
        Dst = (widx == 0) ? g_k : (widx == 1) ? g_v : g_sr;
        sig = (widx == 2);
    } else {
        widx = 3; ncol0 = bx * 128; Dst = outp;
    }
    const __half* Asrc = (MODE == 0) ? g_xsh : g_pv;
    const __half* Bw = g_whT + widx * 65536;

    int crow[4], ch8[4];
    uint32_t sAaddr[4], sBaddr[4];
    #pragma unroll
    for (int q = 0; q < 4; q++) {
        int id = tid + q * 256;
        crow[q] = id >> 3;
        ch8[q] = (id & 7) * 8;                      // half offset in row
        sAaddr[q] = (uint32_t)__cvta_generic_to_shared(&smh[crow[q] * 72 + ch8[q]]);
        sBaddr[q] = (uint32_t)__cvta_generic_to_shared(&smh[18432 + crow[q] * 72 + ch8[q]]);
    }

    float acc[4][4][4];
    #pragma unroll
    for (int i = 0; i < 4; i++)
        #pragma unroll
        for (int j = 0; j < 4; j++)
            #pragma unroll
            for (int e = 0; e < 4; e++)
                acc[i][j][e] = 0.0f;

    auto issue = [&](int kt, int st) {
        int k0 = kt * 64;
        uint32_t so = st * 18432;                   // bytes between stages
        #pragma unroll
        for (int q = 0; q < 4; q++) {
            cpa16(sAaddr[q] + so, Asrc + (size_t)(m0 + crow[q]) * CC + k0 + ch8[q]);
            cpa16(sBaddr[q] + so, Bw + (size_t)(ncol0 + crow[q]) * CC + k0 + ch8[q]);
        }
    };

    issue(0, 0);
    CP_COMMIT();

    for (int kt = 0; kt < 4; kt++) {
        int st = kt & 1;
        if (kt + 1 < 4) { issue(kt + 1, st ^ 1); CP_COMMIT(); CP_WAIT1(); }
        else            { CP_WAIT0(); }
        __syncthreads();

        const __half* Ab = smh + st * 9216;
        const __half* Bb = smh + 18432 + st * 9216;
        #pragma unroll
        for (int ks = 0; ks < 4; ks++) {
            int kk = ks * 16;
            uint32_t a[4][4], b[4][2];
            #pragma unroll
            for (int mf = 0; mf < 4; mf++) {
                int r = wm * 64 + mf * 16 + qr;
                a[mf][0] = *(const uint32_t*)&Ab[r * 72       + kk + 2 * qc    ];
                a[mf][1] = *(const uint32_t*)&Ab[(r + 8) * 72 + kk + 2 * qc    ];
                a[mf][2] = *(const uint32_t*)&Ab[r * 72       + kk + 2 * qc + 8];
                a[mf][3] = *(const uint32_t*)&Ab[(r + 8) * 72 + kk + 2 * qc + 8];
            }
            #pragma unroll
            for (int nf = 0; nf < 4; nf++) {
                int n = wn * 32 + nf * 8 + qr;
                b[nf][0] = *(const uint32_t*)&Bb[n * 72 + kk + 2 * qc    ];
                b[nf][1] = *(const uint32_t*)&Bb[n * 72 + kk + 2 * qc + 8];
            }
            #pragma unroll
            for (int mf = 0; mf < 4; mf++)
                #pragma unroll
                for (int nf = 0; nf < 4; nf++)
                    mma16(acc[mf][nf], a[mf], b[nf]);
        }
        __syncthreads();
    }

    #pragma unroll
    for (int mf = 0; mf < 4; mf++) {
        int row = m0 + wm * 64 + mf * 16 + qr;
        #pragma unroll
        for (int nf = 0; nf < 4; nf++) {
            int col = ncol0 + wn * 32 + nf * 8 + qc * 2;
            float v0 = acc[mf][nf][0], v1 = acc[mf][nf][1];
            float v2 = acc[mf][nf][2], v3 = acc[mf][nf][3];
            if (sig) {
                v0 = 1.0f / (1.0f + __expf(-v0));
                v1 = 1.0f / (1.0f + __expf(-v1));
                v2 = 1.0f / (1.0f + __expf(-v2));
                v3 = 1.0f / (1.0f + __expf(-v3));
            }
            *(float2*)&Dst[(size_t)row * CC + col]       = make_float2(v0, v1);
            *(float2*)&Dst[(size_t)(row + 8) * CC + col] = make_float2(v2, v3);
        }
    }
}

// ---------------- scan phase 1: chunk aggregates -----------------------------
template<int JM>
__global__ __launch_bounds__(256, 2) void scan_p1(const float* __restrict__ sd, int j)
{
    int c = threadIdx.x;
    int b = blockIdx.x >> 8;
    int ch = blockIdx.x & 255;
    float wneg = -__expf(sd[j * CC + c] * (1.0f / 4096.0f));
    int base = b * TT * CC + c;
    int s0 = ch * CLEN;

    float kk[CLEN], vv[CLEN];
    #pragma unroll
    for (int i = 0; i < CLEN; i++) {
        int t = seqmap<JM>(s0 + i);
        kk[i] = g_k[base + t * CC];
        vv[i] = g_v[base + t * CC];
    }
    int ai = (b * NCH + ch) * CC + c;

    float a = 0.0f, bb = 0.0f, p = -1e38f;
    #pragma unroll
    for (int i = 0; i < CLEN; i++)
        step1(a, bb, p, wneg, kk[i], vv[i]);
    g_fA[ai] = a; g_fB[ai] = bb; g_fP[ai] = p;

    a = 0.0f; bb = 0.0f; p = -1e38f;
    #pragma unroll
    for (int i = CLEN - 1; i >= 0; i--)
        step1(a, bb, p, wneg, kk[i], vv[i]);
    g_bAg[ai] = a; g_bBg[ai] = bb; g_bPg[ai] = p;
}

// ---------------- scan phase 2a: intra-super prefixes/suffixes + super aggs --
__global__ __launch_bounds__(256) void scan_p2a(const float* __restrict__ sd, int j)
{
    int c = threadIdx.x;
    int bx = blockIdx.x;               // 512 blocks: dir(1) b(4) sg(4)
    int dir = bx >> 8;
    int b = (bx >> 4) & 15;
    int sg = bx & 15;
    float wneg = -__expf(sd[j * CC + c] * (1.0f / 4096.0f));
    float dec = (float)CLEN * wneg;
    int si = (b * SG + sg) * CC + c;
    float a = 0.0f, bb = 0.0f, p = -1e38f;

    if (dir == 0) {
        #pragma unroll
        for (int chl = 0; chl < 16; chl++) {
            int ai = (b * NCH + sg * 16 + chl) * CC + c;
            g_pA[ai] = a; g_pB[ai] = bb; g_pP[ai] = p;
            stepagg(a, bb, p, dec, g_fA[ai], g_fB[ai], g_fP[ai]);
        }
        g_sgA[si] = a; g_sgB[si] = bb; g_sgP[si] = p;
    } else {
        #pragma unroll
        for (int chl = 15; chl >= 0; chl--) {
            int ai = (b * NCH + sg * 16 + chl) * CC + c;
            g_sA[ai] = a; g_sB[ai] = bb; g_sP[ai] = p;
            stepagg(a, bb, p, dec, g_bAg[ai], g_bBg[ai], g_bPg[ai]);
        }
        g_sgbA[si] = a; g_sgbB[si] = bb; g_sgbP[si] = p;
    }
}

// ---------------- scan phase 2b: super-level exclusive scan ------------------
__global__ __launch_bounds__(256) void scan_p2b(const float* __restrict__ sd, int j)
{
    int idx = blockIdx.x * 256 + threadIdx.x;   // 0..8191: dir(1) b(4) c(8)
    int dir = idx >> 12;
    int b = (idx >> 8) & 15;
    int c = idx & 255;
    float wneg = -__expf(sd[j * CC + c] * (1.0f / 4096.0f));
    float dec = (float)(CLEN * 16) * wneg;
    float a = 0.0f, bb = 0.0f, p = -1e38f;

    if (dir == 0) {
        #pragma unroll
        for (int sg = 0; sg < SG; sg++) {
            int si = (b * SG + sg) * CC + c;
            g_SPA[si] = a; g_SPB[si] = bb; g_SPP[si] = p;
            stepagg(a, bb, p, dec, g_sgA[si], g_sgB[si], g_sgP[si]);
        }
    } else {
        #pragma unroll
        for (int sg = SG - 1; sg >= 0; sg--) {
            int si = (b * SG + sg) * CC + c;
            g_SSA[si] = a; g_SSB[si] = bb; g_SSP[si] = p;
            stepagg(a, bb, p, dec, g_sgbA[si], g_sgbB[si], g_sgbP[si]);
        }
    }
}

// ---------------- scan phase 3 -----------------------------------------------
// FUSE=0: writes fp32 v. FUSE=1 (final rec): writes fp16 sr*v product to g_pv.
template<int JM, int FUSE>
__global__ __launch_bounds__(256) void scan_p3(
    const float* __restrict__ sd, const float* __restrict__ sf, int j)
{
    __shared__ float shA[CLEN][256];
    __shared__ float shB[CLEN][256];

    int c = threadIdx.x;
    int b = blockIdx.x >> 8;
    int ch = blockIdx.x & 255;
    int sg = ch >> 4, chl = ch & 15;
    float wneg = -__expf(sd[j * CC + c] * (1.0f / 4096.0f));
    float u = sf[j * CC + c] * (1.0f / 4096.0f);
    int base = b * TT * CC + c;
    int ai = (b * NCH + ch) * CC + c;
    int si = (b * SG + sg) * CC + c;
    int s0 = ch * CLEN;

    // full fwd prefix = super prefix (shift chl*16 steps) ⊕ intra prefix
    float af, bf, pf;
    {
        float pa = g_pA[ai], pb = g_pB[ai], pp = g_pP[ai];
        float Sa = g_SPA[si], Sb = g_SPB[si], Sp = g_SPP[si];
        float sh = Sp + (float)(chl * CLEN) * wneg;
        float q = fmaxf(sh, pp);
        float e1 = __expf(sh - q), e2 = __expf(pp - q);
        af = e1 * Sa + e2 * pa; bf = e1 * Sb + e2 * pb; pf = q;
    }
    // full suffix = intra suffix ⊕ super suffix (shift (15-chl)*16 steps)
    float ab, bbv, pbw;
    {
        float sa = g_sA[ai], sb = g_sB[ai], sp = g_sP[ai];
        float Ta = g_SSA[si], Tb = g_SSB[si], Tp = g_SSP[si];
        float sh = Tp + (float)((15 - chl) * CLEN) * wneg;
        float q = fmaxf(sp, sh);
        float e1 = __expf(sp - q), e2 = __expf(sh - q);
        ab = e1 * sa + e2 * Ta; bbv = e1 * sb + e2 * Tb; pbw = q;
    }

    float kk[CLEN], vv[CLEN];
    #pragma unroll
    for (int i = 0; i < CLEN; i++) {
        int t = seqmap<JM>(s0 + i);
        kk[i] = g_k[base + t * CC];
        vv[i] = g_v[base + t * CC];
    }

    // forward pass: record pre-update fwd carries (A,B in smem, P in regs)
    float fP[CLEN];
    #pragma unroll
    for (int i = 0; i < CLEN; i++) {
        shA[i][c] = af; shB[i][c] = bf; fP[i] = pf;
        step1(af, bf, pf, wneg, kk[i], vv[i]);
    }

    // backward pass: combine fwd + running bwd + self, then fold element in
    #pragma unroll
    for (int i = CLEN - 1; i >= 0; i--) {
        int t = seqmap<JM>(s0 + i);
        int ti = base + t * CC;
        float ps = u + kk[i];
        float q = fmaxf(fmaxf(fP[i], pbw), ps);
        float ef = __expf(fP[i] - q);
        float eb = __expf(pbw - q);
        float es = __expf(ps - q);
        float num = ef * shA[i][c] + eb * ab + es * vv[i];
        float den = ef * shB[i][c] + eb * bbv + es;
        float r = num / den;
        if (FUSE) {
            g_pv[ti] = __float2half_rn(g_sr[ti] * r);
        } else {
            g_v[ti] = r;
        }
        step1(ab, bbv, pbw, wneg, kk[i], vv[i]);
    }
}

// ---------------- launcher ---------------------------------------------------
extern "C" void kernel_launch(void* const* d_in, const int* in_sizes, int n_in,
                              void* d_out, int out_size)
{
    const float *x = nullptr, *alpha = nullptr, *w1 = nullptr, *w3 = nullptr, *w5 = nullptr;
    const float* Wm[4] = {nullptr, nullptr, nullptr, nullptr};
    const float* S2[2] = {nullptr, nullptr};
    int nW = 0, nS = 0;
    for (int i = 0; i < n_in; i++) {
        int sz = in_sizes[i];
        const float* p = (const float*)d_in[i];
        if      (sz == NELEM) x = p;
        else if (sz == 4)     alpha = p;
        else if (sz == 256)   w1 = p;
        else if (sz == 2304)  w3 = p;
        else if (sz == 6400)  w5 = p;
        else if (sz == 65536) { if (nW < 4) Wm[nW++] = p; }
        else if (sz == 512)   { if (nS < 2) S2[nS++] = p; }
    }

    const int GSMEM = 36864 * 2;   // 73,728 B: 2-stage A+B fp16 tiles
    cudaFuncSetAttribute(gemm_mma<0>, cudaFuncAttributeMaxDynamicSharedMemorySize, GSMEM);
    cudaFuncSetAttribute(gemm_mma<1>, cudaFuncAttributeMaxDynamicSharedMemorySize, GSMEM);

    omni_kernel<<<BB * 64, 256>>>(x, alpha, w1, w3, w5);
    prep_kernel<<<dim3(256, 4), 256>>>(Wm[0], Wm[1], Wm[2], Wm[3]);

    gemm_mma<0><<<dim3(6, 512), 256, GSMEM>>>(nullptr);

    scan_p1<0><<<BB * NCH, 256>>>(S2[0], 0);
    scan_p2a<<<512, 256>>>(S2[0], 0);
    scan_p2b<<<32, 256>>>(S2[0], 0);
    scan_p3<0, 0><<<BB * NCH, 256>>>(S2[0], S2[1], 0);

    scan_p1<1><<<BB * NCH, 256>>>(S2[0], 1);
    scan_p2a<<<512, 256>>>(S2[0], 1);
    scan_p2b<<<32, 256>>>(S2[0], 1);
    scan_p3<1, 1><<<BB * NCH, 256>>>(S2[0], S2[1], 1);

    gemm_mma<1><<<dim3(2, 512), 256, GSMEM>>>((float*)d_out);
}

// round 12
// speedup vs baseline: 2.5246x; 1.0075x over previous
#include <cuda_runtime.h>
#include <cuda_fp16.h>
#include <cstdint>

#define BB   16
#define TT   4096
#define CC   256
#define NCH  256          // chunks per scan
#define CLEN 16           // T / NCH
#define SG   16           // supergroups (16 chunks each)
#define NELEM (BB*TT*CC)
#define NAGG  (BB*NCH*CC)
#define NSUP  (BB*SG*CC)

__device__ __half g_xsh[NELEM];    // omni output, fp16 (GEMM0 A)
__device__ __half g_pv [NELEM];    // fused sr*v product, fp16 (GEMM1 A)
__device__ __half g_whT[4 * 65536];// transposed fp16 weights [w][n][k]
__device__ float  g_k  [NELEM];    // fp32: lives in the exponent
__device__ __half g_vh [NELEM];    // fp16 v
__device__ __half g_srh[NELEM];    // fp16 sigmoid(r)
// chunk-level aggregates and intra-super exclusive prefixes/suffixes
__device__ float g_fA[NAGG], g_fB[NAGG], g_fP[NAGG];
__device__ float g_bAg[NAGG], g_bBg[NAGG], g_bPg[NAGG];
__device__ float g_pA[NAGG], g_pB[NAGG], g_pP[NAGG];
__device__ float g_sA[NAGG], g_sB[NAGG], g_sP[NAGG];
// super-level
__device__ float g_sgA[NSUP], g_sgB[NSUP], g_sgP[NSUP];
__device__ float g_sgbA[NSUP], g_sgbB[NSUP], g_sgbP[NSUP];
__device__ float g_SPA[NSUP], g_SPB[NSUP], g_SPP[NSUP];
__device__ float g_SSA[NSUP], g_SSB[NSUP], g_SSP[NSUP];

__device__ __forceinline__ void mma16(float* c, const uint32_t* a, const uint32_t* b) {
    asm volatile(
        "mma.sync.aligned.m16n8k16.row.col.f32.f16.f16.f32 "
        "{%0,%1,%2,%3}, {%4,%5,%6,%7}, {%8,%9}, {%0,%1,%2,%3};"
        : "+f"(c[0]), "+f"(c[1]), "+f"(c[2]), "+f"(c[3])
        : "r"(a[0]), "r"(a[1]), "r"(a[2]), "r"(a[3]), "r"(b[0]), "r"(b[1]));
}

__device__ __forceinline__ void cpa16(uint32_t saddr, const void* gaddr) {
    asm volatile("cp.async.cg.shared.global [%0], [%1], 16;"
                 :: "r"(saddr), "l"(gaddr) : "memory");
}
#define CP_COMMIT() asm volatile("cp.async.commit_group;" ::: "memory")
#define CP_WAIT1()  asm volatile("cp.async.wait_group 1;" ::: "memory")
#define CP_WAIT0()  asm volatile("cp.async.wait_group 0;" ::: "memory")

template<int JM>
__device__ __forceinline__ int seqmap(int s) {
    return (JM == 0) ? s : (((s & 63) << 6) | (s >> 6));
}

// single-exp scan step: q = max(p+sh, kt); one of e1,e2 is 1.
__device__ __forceinline__ void step1(float& a, float& b, float& p,
                                      float sh, float kt, float vt) {
    float d = p + sh - kt;
    float e = __expf(-fabsf(d));
    bool gt = d > 0.0f;
    float e1 = gt ? 1.0f : e;
    float e2 = gt ? e : 1.0f;
    a = e1 * a + e2 * vt;
    b = e1 * b + e2;
    p = gt ? (p + sh) : kt;
}
__device__ __forceinline__ void stepagg(float& a, float& b, float& p, float sh,
                                        float Ag, float Bg, float Pg) {
    float d = p + sh - Pg;
    float e = __expf(-fabsf(d));
    bool gt = d > 0.0f;
    float e1 = gt ? 1.0f : e;
    float e2 = gt ? e : 1.0f;
    a = e1 * a + e2 * Ag;
    b = e1 * b + e2 * Bg;
    p = gt ? (p + sh) : Pg;
}

// ---------------- omni_shift (fp16 output) -----------------------------------
__global__ __launch_bounds__(256) void omni_kernel(
    const float* __restrict__ x, const float* __restrict__ alpha,
    const float* __restrict__ w1, const float* __restrict__ w3,
    const float* __restrict__ w5)
{
    int c = threadIdx.x;
    int b = blockIdx.x >> 6;
    int w = blockIdx.x & 63;
    float a0 = alpha[0], a1 = alpha[1], a2 = alpha[2], a3 = alpha[3];

    float coef[5][5];
    #pragma unroll
    for (int r = 0; r < 5; r++)
        #pragma unroll
        for (int d = 0; d < 5; d++)
            coef[r][d] = a3 * w5[c * 25 + r * 5 + d];
    #pragma unroll
    for (int r = 0; r < 3; r++)
        #pragma unroll
        for (int d = 0; d < 3; d++)
            coef[r + 1][d + 1] += a2 * w3[c * 9 + r * 3 + d];
    coef[2][2] += a0 + a1 * w1[c];

    const float* xb = x + (size_t)b * TT * CC + c;
    __half* ob = g_xsh + (size_t)b * TT * CC + c;

    float win[5][5];
    #pragma unroll
    for (int r = 0; r < 5; r++) {
        int hr = r - 2;
        #pragma unroll
        for (int d = 0; d < 5; d++) {
            int wx = w + d - 2;
            win[r][d] = (hr >= 0 && wx >= 0 && wx < 64) ? xb[(hr * 64 + wx) * CC] : 0.0f;
        }
    }
    for (int h = 0; h < 64; h++) {
        float acc = 0.0f;
        #pragma unroll
        for (int r = 0; r < 5; r++)
            #pragma unroll
            for (int d = 0; d < 5; d++)
                acc = fmaf(coef[r][d], win[r][d], acc);
        ob[(h * 64 + w) * CC] = __float2half_rn(acc);
        #pragma unroll
        for (int r = 0; r < 4; r++)
            #pragma unroll
            for (int d = 0; d < 5; d++)
                win[r][d] = win[r + 1][d];
        int hr = h + 3;
        #pragma unroll
        for (int d = 0; d < 5; d++) {
            int wx = w + d - 2;
            win[4][d] = (hr < 64 && wx >= 0 && wx < 64) ? xb[(hr * 64 + wx) * CC] : 0.0f;
        }
    }
}

// ---------------- weight transpose + fp16 round ------------------------------
__global__ void prep_kernel(const float* __restrict__ W0, const float* __restrict__ W1,
                            const float* __restrict__ W2, const float* __restrict__ W3)
{
    int widx = blockIdx.y;
    int n = blockIdx.x;
    int k = threadIdx.x;
    const float* W = (widx == 0) ? W0 : (widx == 1) ? W1 : (widx == 2) ? W2 : W3;
    g_whT[widx * 65536 + n * 256 + k] = __float2half_rn(W[k * 256 + n]);
}

// ---------------- fp16 mma.sync GEMM, cp.async 2-stage pipeline --------------
// MODE 0: A=g_xsh, bx 0..5 -> {Wk|Wv|Wr} halves -> g_k (fp32) / g_vh / g_srh
// MODE 1: A=g_pv, B=WoT, writes fp32 outp, bx 0..1
template<int MODE>
__global__ __launch_bounds__(256) void gemm_mma(float* __restrict__ outp)
{
    extern __shared__ __half smh[];

    int tid = threadIdx.x;
    int wid = tid >> 5, lane = tid & 31;
    int wm = wid & 1, wn = wid >> 1;
    int qr = lane >> 2, qc = lane & 3;
    int bx = blockIdx.x, by = blockIdx.y;
    int m0 = by * 128;

    int widx, ncol0;
    if (MODE == 0) { widx = bx >> 1; ncol0 = (bx & 1) * 128; }
    else           { widx = 3;       ncol0 = bx * 128; }
    const __half* Asrc = (MODE == 0) ? g_xsh : g_pv;
    const __half* Bw = g_whT + widx * 65536;

    int crow[4], ch8[4];
    uint32_t sAaddr[4], sBaddr[4];
    #pragma unroll
    for (int q = 0; q < 4; q++) {
        int id = tid + q * 256;
        crow[q] = id >> 3;
        ch8[q] = (id & 7) * 8;
        sAaddr[q] = (uint32_t)__cvta_generic_to_shared(&smh[crow[q] * 72 + ch8[q]]);
        sBaddr[q] = (uint32_t)__cvta_generic_to_shared(&smh[18432 + crow[q] * 72 + ch8[q]]);
    }

    float acc[4][4][4];
    #pragma unroll
    for (int i = 0; i < 4; i++)
        #pragma unroll
        for (int j = 0; j < 4; j++)
            #pragma unroll
            for (int e = 0; e < 4; e++)
                acc[i][j][e] = 0.0f;

    auto issue = [&](int kt, int st) {
        int k0 = kt * 64;
        uint32_t so = st * 18432;
        #pragma unroll
        for (int q = 0; q < 4; q++) {
            cpa16(sAaddr[q] + so, Asrc + (size_t)(m0 + crow[q]) * CC + k0 + ch8[q]);
            cpa16(sBaddr[q] + so, Bw + (size_t)(ncol0 + crow[q]) * CC + k0 + ch8[q]);
        }
    };

    issue(0, 0);
    CP_COMMIT();

    for (int kt = 0; kt < 4; kt++) {
        int st = kt & 1;
        if (kt + 1 < 4) { issue(kt + 1, st ^ 1); CP_COMMIT(); CP_WAIT1(); }
        else            { CP_WAIT0(); }
        __syncthreads();

        const __half* Ab = smh + st * 9216;
        const __half* Bb = smh + 18432 + st * 9216;
        #pragma unroll
        for (int ks = 0; ks < 4; ks++) {
            int kk = ks * 16;
            uint32_t a[4][4], b[4][2];
            #pragma unroll
            for (int mf = 0; mf < 4; mf++) {
                int r = wm * 64 + mf * 16 + qr;
                a[mf][0] = *(const uint32_t*)&Ab[r * 72       + kk + 2 * qc    ];
                a[mf][1] = *(const uint32_t*)&Ab[(r + 8) * 72 + kk + 2 * qc    ];
                a[mf][2] = *(const uint32_t*)&Ab[r * 72       + kk + 2 * qc + 8];
                a[mf][3] = *(const uint32_t*)&Ab[(r + 8) * 72 + kk + 2 * qc + 8];
            }
            #pragma unroll
            for (int nf = 0; nf < 4; nf++) {
                int n = wn * 32 + nf * 8 + qr;
                b[nf][0] = *(const uint32_t*)&Bb[n * 72 + kk + 2 * qc    ];
                b[nf][1] = *(const uint32_t*)&Bb[n * 72 + kk + 2 * qc + 8];
            }
            #pragma unroll
            for (int mf = 0; mf < 4; mf++)
                #pragma unroll
                for (int nf = 0; nf < 4; nf++)
                    mma16(acc[mf][nf], a[mf], b[nf]);
        }
        __syncthreads();
    }

    // epilogue
    #pragma unroll
    for (int mf = 0; mf < 4; mf++) {
        int row = m0 + wm * 64 + mf * 16 + qr;
        #pragma unroll
        for (int nf = 0; nf < 4; nf++) {
            int col = ncol0 + wn * 32 + nf * 8 + qc * 2;
            float v0 = acc[mf][nf][0], v1 = acc[mf][nf][1];
            float v2 = acc[mf][nf][2], v3 = acc[mf][nf][3];
            if (MODE == 1) {
                *(float2*)&outp[(size_t)row * CC + col]       = make_float2(v0, v1);
                *(float2*)&outp[(size_t)(row + 8) * CC + col] = make_float2(v2, v3);
            } else if (widx == 0) {
                *(float2*)&g_k[(size_t)row * CC + col]       = make_float2(v0, v1);
                *(float2*)&g_k[(size_t)(row + 8) * CC + col] = make_float2(v2, v3);
            } else if (widx == 1) {
                *(__half2*)&g_vh[(size_t)row * CC + col]       = __floats2half2_rn(v0, v1);
                *(__half2*)&g_vh[(size_t)(row + 8) * CC + col] = __floats2half2_rn(v2, v3);
            } else {
                v0 = 1.0f / (1.0f + __expf(-v0));
                v1 = 1.0f / (1.0f + __expf(-v1));
                v2 = 1.0f / (1.0f + __expf(-v2));
                v3 = 1.0f / (1.0f + __expf(-v3));
                *(__half2*)&g_srh[(size_t)row * CC + col]       = __floats2half2_rn(v0, v1);
                *(__half2*)&g_srh[(size_t)(row + 8) * CC + col] = __floats2half2_rn(v2, v3);
            }
        }
    }
}

// ---------------- scan phase 1: chunk aggregates -----------------------------
template<int JM>
__global__ __launch_bounds__(256, 2) void scan_p1(const float* __restrict__ sd, int j)
{
    int c = threadIdx.x;
    int b = blockIdx.x >> 8;
    int ch = blockIdx.x & 255;
    float wneg = -__expf(sd[j * CC + c] * (1.0f / 4096.0f));
    int base = b * TT * CC + c;
    int s0 = ch * CLEN;

    float kk[CLEN], vv[CLEN];
    #pragma unroll
    for (int i = 0; i < CLEN; i++) {
        int t = seqmap<JM>(s0 + i);
        kk[i] = g_k[base + t * CC];
        vv[i] = __half2float(g_vh[base + t * CC]);
    }
    int ai = (b * NCH + ch) * CC + c;

    float a = 0.0f, bb = 0.0f, p = -1e38f;
    #pragma unroll
    for (int i = 0; i < CLEN; i++)
        step1(a, bb, p, wneg, kk[i], vv[i]);
    g_fA[ai] = a; g_fB[ai] = bb; g_fP[ai] = p;

    a = 0.0f; bb = 0.0f; p = -1e38f;
    #pragma unroll
    for (int i = CLEN - 1; i >= 0; i--)
        step1(a, bb, p, wneg, kk[i], vv[i]);
    g_bAg[ai] = a; g_bBg[ai] = bb; g_bPg[ai] = p;
}

// ---------------- scan phase 2a: intra-super prefixes/suffixes + super aggs --
__global__ __launch_bounds__(256) void scan_p2a(const float* __restrict__ sd, int j)
{
    int c = threadIdx.x;
    int bx = blockIdx.x;               // 512 blocks: dir(1) b(4) sg(4)
    int dir = bx >> 8;
    int b = (bx >> 4) & 15;
    int sg = bx & 15;
    float wneg = -__expf(sd[j * CC + c] * (1.0f / 4096.0f));
    float dec = (float)CLEN * wneg;
    int si = (b * SG + sg) * CC + c;
    float a = 0.0f, bb = 0.0f, p = -1e38f;

    if (dir == 0) {
        #pragma unroll
        for (int chl = 0; chl < 16; chl++) {
            int ai = (b * NCH + sg * 16 + chl) * CC + c;
            g_pA[ai] = a; g_pB[ai] = bb; g_pP[ai] = p;
            stepagg(a, bb, p, dec, g_fA[ai], g_fB[ai], g_fP[ai]);
        }
        g_sgA[si] = a; g_sgB[si] = bb; g_sgP[si] = p;
    } else {
        #pragma unroll
        for (int chl = 15; chl >= 0; chl--) {
            int ai = (b * NCH + sg * 16 + chl) * CC + c;
            g_sA[ai] = a; g_sB[ai] = bb; g_sP[ai] = p;
            stepagg(a, bb, p, dec, g_bAg[ai], g_bBg[ai], g_bPg[ai]);
        }
        g_sgbA[si] = a; g_sgbB[si] = bb; g_sgbP[si] = p;
    }
}

// ---------------- scan phase 2b: super-level exclusive scan ------------------
__global__ __launch_bounds__(256) void scan_p2b(const float* __restrict__ sd, int j)
{
    int idx = blockIdx.x * 256 + threadIdx.x;   // 0..8191: dir(1) b(4) c(8)
    int dir = idx >> 12;
    int b = (idx >> 8) & 15;
    int c = idx & 255;
    float wneg = -__expf(sd[j * CC + c] * (1.0f / 4096.0f));
    float dec = (float)(CLEN * 16) * wneg;
    float a = 0.0f, bb = 0.0f, p = -1e38f;

    if (dir == 0) {
        #pragma unroll
        for (int sg = 0; sg < SG; sg++) {
            int si = (b * SG + sg) * CC + c;
            g_SPA[si] = a; g_SPB[si] = bb; g_SPP[si] = p;
            stepagg(a, bb, p, dec, g_sgA[si], g_sgB[si], g_sgP[si]);
        }
    } else {
        #pragma unroll
        for (int sg = SG - 1; sg >= 0; sg--) {
            int si = (b * SG + sg) * CC + c;
            g_SSA[si] = a; g_SSB[si] = bb; g_SSP[si] = p;
            stepagg(a, bb, p, dec, g_sgbA[si], g_sgbB[si], g_sgbP[si]);
        }
    }
}

// ---------------- scan phase 3 -----------------------------------------------
// FUSE=0: writes fp16 v. FUSE=1 (final rec): writes fp16 sr*v product to g_pv.
template<int JM, int FUSE>
__global__ __launch_bounds__(256) void scan_p3(
    const float* __restrict__ sd, const float* __restrict__ sf, int j)
{
    __shared__ float shA[CLEN][256];
    __shared__ float shB[CLEN][256];

    int c = threadIdx.x;
    int b = blockIdx.x >> 8;
    int ch = blockIdx.x & 255;
    int sg = ch >> 4, chl = ch & 15;
    float wneg = -__expf(sd[j * CC + c] * (1.0f / 4096.0f));
    float u = sf[j * CC + c] * (1.0f / 4096.0f);
    int base = b * TT * CC + c;
    int ai = (b * NCH + ch) * CC + c;
    int si = (b * SG + sg) * CC + c;
    int s0 = ch * CLEN;

    // full fwd prefix = super prefix (shift chl*16 steps) ⊕ intra prefix
    float af, bf, pf;
    {
        float pa = g_pA[ai], pb = g_pB[ai], pp = g_pP[ai];
        float Sa = g_SPA[si], Sb = g_SPB[si], Sp = g_SPP[si];
        float sh = Sp + (float)(chl * CLEN) * wneg;
        float q = fmaxf(sh, pp);
        float e1 = __expf(sh - q), e2 = __expf(pp - q);
        af = e1 * Sa + e2 * pa; bf = e1 * Sb + e2 * pb; pf = q;
    }
    // full suffix = intra suffix ⊕ super suffix (shift (15-chl)*16 steps)
    float ab, bbv, pbw;
    {
        float sa = g_sA[ai], sb = g_sB[ai], sp = g_sP[ai];
        float Ta = g_SSA[si], Tb = g_SSB[si], Tp = g_SSP[si];
        float sh = Tp + (float)((15 - chl) * CLEN) * wneg;
        float q = fmaxf(sp, sh);
        float e1 = __expf(sp - q), e2 = __expf(sh - q);
        ab = e1 * sa + e2 * Ta; bbv = e1 * sb + e2 * Tb; pbw = q;
    }

    float kk[CLEN], vv[CLEN];
    #pragma unroll
    for (int i = 0; i < CLEN; i++) {
        int t = seqmap<JM>(s0 + i);
        kk[i] = g_k[base + t * CC];
        vv[i] = __half2float(g_vh[base + t * CC]);
    }

    // forward pass: record pre-update fwd carries (A,B in smem, P in regs)
    float fP[CLEN];
    #pragma unroll
    for (int i = 0; i < CLEN; i++) {
        shA[i][c] = af; shB[i][c] = bf; fP[i] = pf;
        step1(af, bf, pf, wneg, kk[i], vv[i]);
    }

    // backward pass: combine fwd + running bwd + self, then fold element in
    #pragma unroll
    for (int i = CLEN - 1; i >= 0; i--) {
        int t = seqmap<JM>(s0 + i);
        int ti = base + t * CC;
        float ps = u + kk[i];
        float q = fmaxf(fmaxf(fP[i], pbw), ps);
        float ef = __expf(fP[i] - q);
        float eb = __expf(pbw - q);
        float es = __expf(ps - q);
        float num = ef * shA[i][c] + eb * ab + es * vv[i];
        float den = ef * shB[i][c] + eb * bbv + es;
        float r = num / den;
        if (FUSE) {
            g_pv[ti] = __float2half_rn(__half2float(g_srh[ti]) * r);
        } else {
            g_vh[ti] = __float2half_rn(r);
        }
        step1(ab, bbv, pbw, wneg, kk[i], vv[i]);
    }
}

// ---------------- launcher ---------------------------------------------------
extern "C" void kernel_launch(void* const* d_in, const int* in_sizes, int n_in,
                              void* d_out, int out_size)
{
    const float *x = nullptr, *alpha = nullptr, *w1 = nullptr, *w3 = nullptr, *w5 = nullptr;
    const float* Wm[4] = {nullptr, nullptr, nullptr, nullptr};
    const float* S2[2] = {nullptr, nullptr};
    int nW = 0, nS = 0;
    for (int i = 0; i < n_in; i++) {
        int sz = in_sizes[i];
        const float* p = (const float*)d_in[i];
        if      (sz == NELEM) x = p;
        else if (sz == 4)     alpha = p;
        else if (sz == 256)   w1 = p;
        else if (sz == 2304)  w3 = p;
        else if (sz == 6400)  w5 = p;
        else if (sz == 65536) { if (nW < 4) Wm[nW++] = p; }
        else if (sz == 512)   { if (nS < 2) S2[nS++] = p; }
    }

    const int GSMEM = 36864 * 2;   // 73,728 B: 2-stage A+B fp16 tiles
    cudaFuncSetAttribute(gemm_mma<0>, cudaFuncAttributeMaxDynamicSharedMemorySize, GSMEM);
    cudaFuncSetAttribute(gemm_mma<1>, cudaFuncAttributeMaxDynamicSharedMemorySize, GSMEM);

    omni_kernel<<<BB * 64, 256>>>(x, alpha, w1, w3, w5);
    prep_kernel<<<dim3(256, 4), 256>>>(Wm[0], Wm[1], Wm[2], Wm[3]);

    gemm_mma<0><<<dim3(6, 512), 256, GSMEM>>>(nullptr);

    scan_p1<0><<<BB * NCH, 256>>>(S2[0], 0);
    scan_p2a<<<512, 256>>>(S2[0], 0);
    scan_p2b<<<32, 256>>>(S2[0], 0);
    scan_p3<0, 0><<<BB * NCH, 256>>>(S2[0], S2[1], 0);

    scan_p1<1><<<BB * NCH, 256>>>(S2[0], 1);
    scan_p2a<<<512, 256>>>(S2[0], 1);
    scan_p2b<<<32, 256>>>(S2[0], 1);
    scan_p3<1, 1><<<BB * NCH, 256>>>(S2[0], S2[1], 1);

    gemm_mma<1><<<dim3(2, 512), 256, GSMEM>>>((float*)d_out);
}